// round 9
// baseline (speedup 1.0000x reference)
#include <cuda_runtime.h>

// Problem constants
#define HEADS   8
#define DIMH    64
#define NSEQ    512
#define BATCH   32
#define DMODEL  512
#define BH      (BATCH*HEADS)        // 256
#define NQKV    (3*HEADS*DIMH)       // 1536
#define MROWS   (BATCH*NSEQ)         // 16384
#define ATT_SCALE 0.125f             // 64^-0.5

// ---------------- scratch (device globals; no cudaMalloc allowed) -----------
// all of these hold tf32-bit-patterns stored as float words
__device__ float g_q   [BH*NSEQ*DIMH];
__device__ float g_k   [BH*NSEQ*DIMH];
__device__ float g_v   [BH*NSEQ*DIMH];
__device__ float g_ao  [BATCH*NSEQ*DMODEL];
__device__ float g_xtf [MROWS*DMODEL];
__device__ float g_wqkv[DMODEL*NQKV];
__device__ float g_wout[DMODEL*DMODEL];
__device__ float g_rel [1025*DIMH];

// ---------------------------------------------------------------------------
// helpers
// ---------------------------------------------------------------------------
__device__ __forceinline__ unsigned f2tf(float x) {
    unsigned r;
    asm("cvt.rna.tf32.f32 %0, %1;" : "=r"(r) : "f"(x));
    return r;
}

__device__ __forceinline__ void mma_tf32_v(float c[4], const unsigned a[4],
                                           unsigned b0, unsigned b1) {
    asm volatile(
        "mma.sync.aligned.m16n8k8.row.col.f32.tf32.tf32.f32 "
        "{%0,%1,%2,%3}, {%4,%5,%6,%7}, {%8,%9}, {%0,%1,%2,%3};\n"
        : "+f"(c[0]), "+f"(c[1]), "+f"(c[2]), "+f"(c[3])
        : "r"(a[0]), "r"(a[1]), "r"(a[2]), "r"(a[3]), "r"(b0), "r"(b1));
}
#define MMA mma_tf32_v

__device__ __forceinline__ void cp16(void* smem_dst, const void* gsrc) {
    unsigned s = (unsigned)__cvta_generic_to_shared(smem_dst);
    asm volatile("cp.async.cg.shared.global [%0], [%1], 16;\n" :: "r"(s), "l"(gsrc));
}
__device__ __forceinline__ void cp_commit() {
    asm volatile("cp.async.commit_group;\n");
}
template<int Nq>
__device__ __forceinline__ void cp_wait() {
    asm volatile("cp.async.wait_group %0;\n" :: "n"(Nq));
}

// ============================================================================
// cvt kernel: fp32 -> tf32 bit pattern (vectorized)
// ============================================================================
__global__ void __launch_bounds__(256) cvt_kernel(const float4* __restrict__ src,
                                                  float4* __restrict__ dst, int n4)
{
    int i = blockIdx.x * 256 + threadIdx.x;
    if (i < n4) {
        float4 v = src[i];
        float4 o;
        o.x = __uint_as_float(f2tf(v.x));
        o.y = __uint_as_float(f2tf(v.y));
        o.z = __uint_as_float(f2tf(v.z));
        o.w = __uint_as_float(f2tf(v.w));
        dst[i] = o;
    }
}

// ============================================================================
// mm4: tf32 GEMM, 256 threads / 8 warps (4m x 2n), warp tile 32x64 (mi=2,ni=8).
// 4-stage cp.async ring. Inputs already tf32 bits. ~125 regs/thread ->
// 2 CTAs/SM = 16 warps/SM (2x mm3's warp residency).
// smem/stage: As 128x20 (2560 w) + Bs 16x136 (2176 w); x4 = 75776 B.
// ============================================================================
#define MM4_SMEM_BYTES (4 * (2560 + 2176) * 4)

template<int N, bool SCATTER>
__global__ void __launch_bounds__(256, 2) mm4_kernel(
    const unsigned* __restrict__ A, const unsigned* __restrict__ B,
    const float* __restrict__ bias, float* __restrict__ Cout)
{
    constexpr int K = 512;
    constexpr int ITERS = 32;
    extern __shared__ unsigned sm[];
    unsigned* AsBase = sm;               // 4 stages x 2560
    unsigned* BsBase = sm + 4 * 2560;    // 4 stages x 2176

    const int tid  = threadIdx.x;
    const int w    = tid >> 5, lane = tid & 31;
    const int g    = lane >> 2, tig = lane & 3;
    const int wm   = w >> 1, wn = w & 1;      // 4m x 2n
    const int bm   = blockIdx.y * 128;
    const int bn   = blockIdx.x * 128;

    // loader indices (256 threads; 2 A-chunks + 2 B-chunks per thread)
    const int ar = tid >> 2;           // 0..63 (+64)
    const int ac = (tid & 3) << 2;     // 0,4,8,12
    const int br = tid >> 5;           // 0..7  (+8)
    const int bc = (tid & 31) << 2;    // 0..124

    const unsigned* Ap = A + (size_t)(bm + ar) * K + ac;
    const unsigned* Bp = B + (size_t)br * N + bn + bc;

    auto issue = [&](int it) {
        const int s  = it & 3;
        const int k0 = it * 16;
        unsigned* As = AsBase + s * 2560;
        unsigned* Bs = BsBase + s * 2176;
        cp16(&As[ ar       * 20 + ac], Ap + k0);
        cp16(&As[(ar + 64) * 20 + ac], Ap + (size_t)64 * K + k0);
        cp16(&Bs[ br      * 136 + bc], Bp + (size_t)k0 * N);
        cp16(&Bs[(br + 8) * 136 + bc], Bp + (size_t)(k0 + 8) * N);
    };

    float acc[2][8][4];
#pragma unroll
    for (int mi = 0; mi < 2; ++mi)
#pragma unroll
        for (int ni = 0; ni < 8; ++ni)
#pragma unroll
            for (int e = 0; e < 4; ++e) acc[mi][ni][e] = 0.f;

    // prologue: 3 stages in flight
    issue(0); cp_commit();
    issue(1); cp_commit();
    issue(2); cp_commit();

    for (int it = 0; it < ITERS; ++it) {
        const int cur = it & 3;
        cp_wait<2>();                   // stage `it` complete
        __syncthreads();                // all warps done with the slot being refilled

        if (it + 3 < ITERS) issue(it + 3);
        cp_commit();                    // exactly one commit per iter

        const unsigned* As = AsBase + cur * 2560;
        const unsigned* Bs = BsBase + cur * 2176;
#pragma unroll
        for (int kt = 0; kt < 2; ++kt) {
            unsigned af[2][4];
#pragma unroll
            for (int mi = 0; mi < 2; ++mi) {
                const int base = wm * 32 + mi * 16;
                af[mi][0] = As[(base + g    ) * 20 + kt * 8 + tig    ];
                af[mi][1] = As[(base + g + 8) * 20 + kt * 8 + tig    ];
                af[mi][2] = As[(base + g    ) * 20 + kt * 8 + tig + 4];
                af[mi][3] = As[(base + g + 8) * 20 + kt * 8 + tig + 4];
            }
#pragma unroll
            for (int ni = 0; ni < 8; ++ni) {
                const unsigned b0 = Bs[(kt * 8 + tig    ) * 136 + wn * 64 + ni * 8 + g];
                const unsigned b1 = Bs[(kt * 8 + tig + 4) * 136 + wn * 64 + ni * 8 + g];
                MMA(acc[0][ni], af[0], b0, b1);
                MMA(acc[1][ni], af[1], b0, b1);
            }
        }
    }

    // ---- epilogue ----
    if (SCATTER) {
        const int which = bn >> 9;
        float* dst = (which == 0) ? g_q : (which == 1) ? g_k : g_v;
#pragma unroll
        for (int mi = 0; mi < 2; ++mi) {
            const int r0  = bm + wm * 32 + mi * 16 + g;
            const int bb  = r0 >> 9;
            const int nn0 = r0 & 511;
#pragma unroll
            for (int ni = 0; ni < 8; ++ni) {
                const int c  = bn + wn * 64 + ni * 8 + 2 * tig;
                const int h  = (c & 511) >> 6;
                const int dd = c & 63;
                const size_t rowbase = (size_t)((bb << 3) + h) * NSEQ;
                *(float2*)&dst[(rowbase + nn0    ) * DIMH + dd] = make_float2(
                    __uint_as_float(f2tf(acc[mi][ni][0])),
                    __uint_as_float(f2tf(acc[mi][ni][1])));
                *(float2*)&dst[(rowbase + nn0 + 8) * DIMH + dd] = make_float2(
                    __uint_as_float(f2tf(acc[mi][ni][2])),
                    __uint_as_float(f2tf(acc[mi][ni][3])));
            }
        }
    } else {
#pragma unroll
        for (int mi = 0; mi < 2; ++mi) {
            const int r = bm + wm * 32 + mi * 16 + g;
#pragma unroll
            for (int ni = 0; ni < 8; ++ni) {
                const int c = bn + wn * 64 + ni * 8 + 2 * tig;
                const float2 bv = *(const float2*)&bias[c];
                *(float2*)&Cout[(size_t)r * N + c] =
                    make_float2(acc[mi][ni][0] + bv.x, acc[mi][ni][1] + bv.y);
                *(float2*)&Cout[(size_t)(r + 8) * N + c] =
                    make_float2(acc[mi][ni][2] + bv.x, acc[mi][ni][3] + bv.y);
            }
        }
    }
}

// ============================================================================
// attn5: unchanged from R8 (passing).
// ============================================================================
#define ATT5_SMEM_WORDS (4352 + 4352 + 9216 + 8448)
#define ATT5_SMEM_BYTES (ATT5_SMEM_WORDS * 4)

__global__ void __launch_bounds__(128, 2) attn5_kernel()
{
    extern __shared__ unsigned smu[];
    unsigned* rels   = smu;                    // 64 x 68 (Q staging alias)
    unsigned* ks     = smu + 4352;             // 64 x 68 (l-exchange alias)
    unsigned* vsbuf  = smu + 8704;             // 2 x 64 x 72
    float*    pbs    = (float*)(smu + 17920);  // 64 x 132
    unsigned* ps     = (unsigned*)pbs;

    const int tid  = threadIdx.x;
    const int w    = tid >> 5;
    const int lane = tid & 31;
    const int g    = lane >> 2;
    const int tig  = lane & 3;
    const int wm   = w >> 1, wn = w & 1;

    const int bh = blockIdx.x;
    const int qb = blockIdx.y;
    const int i0 = qb * 64;
    const int rbase = wm * 32 + g;

    const unsigned* qg = (const unsigned*)g_q + ((size_t)bh * NSEQ + i0) * DIMH;
    const unsigned* kg = (const unsigned*)g_k + (size_t)bh * NSEQ * DIMH;
    const unsigned* vg = (const unsigned*)g_v + (size_t)bh * NSEQ * DIMH;
    const unsigned* rg = (const unsigned*)g_rel;

    auto copy_tile = [&](unsigned* dst, const unsigned* src, int st) {
#pragma unroll
        for (int k = 0; k < 8; ++k) {
            const int c  = tid + k * 128;      // chunk 0..1023
            const int r  = c >> 4;             // row 0..63
            const int wo = (c & 15) << 2;      // word offset 0..60
            cp16(&dst[r * st + wo], src + r * DIMH + wo);
        }
    };

    auto issue_tiles = [&](int t) {
        const int j0 = t * 64;
        copy_tile(ks, kg + (size_t)j0 * DIMH, 68);
        copy_tile(vsbuf + (t & 1) * 4608, vg + (size_t)j0 * DIMH, 72);
        copy_tile(rels, rg + (size_t)(i0 + 449 - j0) * DIMH, 68);
    };

    // ---- stage Q into rels via cp.async ----
    copy_tile(rels, qg, 68);
    cp_commit();
    cp_wait<0>();
    __syncthreads();

    // ---- extract Q A-fragments ----
    unsigned qa[2][8][4];
#pragma unroll
    for (int mi = 0; mi < 2; ++mi) {
        const int r0 = rbase + mi * 16;
#pragma unroll
        for (int kt = 0; kt < 8; ++kt) {
            const int c = kt * 8 + tig;
            qa[mi][kt][0] = rels[ r0      * 68 + c    ];
            qa[mi][kt][1] = rels[(r0 + 8) * 68 + c    ];
            qa[mi][kt][2] = rels[ r0      * 68 + c + 4];
            qa[mi][kt][3] = rels[(r0 + 8) * 68 + c + 4];
        }
    }
    __syncthreads();   // rels free

    // ---- prologue: rel chunk(-1) -> pbs half 1 ----
    {
        copy_tile(rels, rg + (size_t)(i0 + 513) * DIMH, 68);
        cp_commit();
        cp_wait<0>();
        __syncthreads();
#pragma unroll
        for (int nt = 0; nt < 4; ++nt) {
            float a0[4] = {0.f,0.f,0.f,0.f}, a1[4] = {0.f,0.f,0.f,0.f};
            const int dr = wn * 32 + nt * 8 + g;
#pragma unroll
            for (int kt = 0; kt < 8; ++kt) {
                const unsigned b0 = rels[dr * 68 + kt * 8 + tig    ];
                const unsigned b1 = rels[dr * 68 + kt * 8 + tig + 4];
                MMA(a0, qa[0][kt], b0, b1);
                MMA(a1, qa[1][kt], b0, b1);
            }
            const int col = 64 + wn * 32 + nt * 8 + 2 * tig;
            *(float2*)&pbs[(rbase     ) * 132 + col] = make_float2(a0[0], a0[1]);
            *(float2*)&pbs[(rbase +  8) * 132 + col] = make_float2(a0[2], a0[3]);
            *(float2*)&pbs[(rbase + 16) * 132 + col] = make_float2(a1[0], a1[1]);
            *(float2*)&pbs[(rbase + 24) * 132 + col] = make_float2(a1[2], a1[3]);
        }
    }
    __syncthreads();

    issue_tiles(0);
    cp_commit();

    float lsum[2][2] = {{0.f, 0.f}, {0.f, 0.f}};
    float o[2][8][4];
#pragma unroll
    for (int mi = 0; mi < 2; ++mi)
#pragma unroll
        for (int nt = 0; nt < 8; ++nt)
#pragma unroll
            for (int e = 0; e < 4; ++e) o[mi][nt][e] = 0.f;

    for (int t = 0; t < 8; ++t) {
        const int h = t & 1;
        const unsigned* vs = vsbuf + h * 4608;

        cp_wait<0>();
        __syncthreads();               // tiles t ready; all warps past PV(t-1)

        // ---- PB new chunk -> pbs half h ----
#pragma unroll
        for (int nt = 0; nt < 4; ++nt) {
            float a0[4] = {0.f,0.f,0.f,0.f}, a1[4] = {0.f,0.f,0.f,0.f};
            const int dr = wn * 32 + nt * 8 + g;
#pragma unroll
            for (int kt = 0; kt < 8; ++kt) {
                const unsigned b0 = rels[dr * 68 + kt * 8 + tig    ];
                const unsigned b1 = rels[dr * 68 + kt * 8 + tig + 4];
                MMA(a0, qa[0][kt], b0, b1);
                MMA(a1, qa[1][kt], b0, b1);
            }
            const int col = h * 64 + wn * 32 + nt * 8 + 2 * tig;
            *(float2*)&pbs[(rbase     ) * 132 + col] = make_float2(a0[0], a0[1]);
            *(float2*)&pbs[(rbase +  8) * 132 + col] = make_float2(a0[2], a0[3]);
            *(float2*)&pbs[(rbase + 16) * 132 + col] = make_float2(a1[0], a1[1]);
            *(float2*)&pbs[(rbase + 24) * 132 + col] = make_float2(a1[2], a1[3]);
        }

        // ---- QK ----
        float s[2][4][4];
#pragma unroll
        for (int nt = 0; nt < 4; ++nt) {
            const int jr = wn * 32 + nt * 8 + g;
#pragma unroll
            for (int mi = 0; mi < 2; ++mi)
                s[mi][nt][0] = s[mi][nt][1] = s[mi][nt][2] = s[mi][nt][3] = 0.f;
#pragma unroll
            for (int kt = 0; kt < 8; ++kt) {
                const unsigned b0 = ks[jr * 68 + kt * 8 + tig    ];
                const unsigned b1 = ks[jr * 68 + kt * 8 + tig + 4];
                MMA(s[0][nt], qa[0][kt], b0, b1);
                MMA(s[1][nt], qa[1][kt], b0, b1);
            }
        }
        __syncthreads();               // pbs chunk visible; ks/rels free

        // ---- bias gather + exp (no max) + partial sums ----
#pragma unroll
        for (int mi = 0; mi < 2; ++mi) {
            const int iA = rbase + mi * 16;
            const int iB = iA + 8;
#pragma unroll
            for (int nt = 0; nt < 4; ++nt) {
                const int jj = wn * 32 + nt * 8 + 2 * tig;
                const int oA0 = iA - jj + 63, oA1 = oA0 - 1;
                const int oB0 = iB - jj + 63, oB1 = oB0 - 1;
                const int pA0 = ((h ^ (oA0 >> 6)) << 6) | (oA0 & 63);
                const int pA1 = ((h ^ (oA1 >> 6)) << 6) | (oA1 & 63);
                const int pB0 = ((h ^ (oB0 >> 6)) << 6) | (oB0 & 63);
                const int pB1 = ((h ^ (oB1 >> 6)) << 6) | (oB1 & 63);
                float e0 = __expf((s[mi][nt][0] + pbs[iA * 132 + pA0]) * ATT_SCALE);
                float e1 = __expf((s[mi][nt][1] + pbs[iA * 132 + pA1]) * ATT_SCALE);
                float e2 = __expf((s[mi][nt][2] + pbs[iB * 132 + pB0]) * ATT_SCALE);
                float e3 = __expf((s[mi][nt][3] + pbs[iB * 132 + pB1]) * ATT_SCALE);
                s[mi][nt][0] = e0; s[mi][nt][1] = e1;
                s[mi][nt][2] = e2; s[mi][nt][3] = e3;
                lsum[mi][0] += e0 + e1;
                lsum[mi][1] += e2 + e3;
            }
        }
        __syncthreads();               // gathers done before P overwrite

        // ---- write P (tf32) into the dead half (h^1) ----
        const int pc0 = (h ^ 1) * 64;
#pragma unroll
        for (int mi = 0; mi < 2; ++mi) {
            const int iA = rbase + mi * 16;
            const int iB = iA + 8;
#pragma unroll
            for (int nt = 0; nt < 4; ++nt) {
                const int c = pc0 + wn * 32 + nt * 8 + 2 * tig;
                ps[iA * 132 + c    ] = f2tf(s[mi][nt][0]);
                ps[iA * 132 + c + 1] = f2tf(s[mi][nt][1]);
                ps[iB * 132 + c    ] = f2tf(s[mi][nt][2]);
                ps[iB * 132 + c + 1] = f2tf(s[mi][nt][3]);
            }
        }
        __syncthreads();               // P visible

        if (t + 1 < 8) issue_tiles(t + 1);
        cp_commit();

#pragma unroll
        for (int kt = 0; kt < 8; ++kt) {
            unsigned pa[2][4];
#pragma unroll
            for (int mi = 0; mi < 2; ++mi) {
                const int iA = rbase + mi * 16;
                const int iB = iA + 8;
                pa[mi][0] = ps[iA * 132 + pc0 + kt * 8 + tig    ];
                pa[mi][1] = ps[iB * 132 + pc0 + kt * 8 + tig    ];
                pa[mi][2] = ps[iA * 132 + pc0 + kt * 8 + tig + 4];
                pa[mi][3] = ps[iB * 132 + pc0 + kt * 8 + tig + 4];
            }
#pragma unroll
            for (int nt = 0; nt < 8; ++nt) {
                const unsigned b0 = vs[(kt * 8 + tig    ) * 72 + nt * 8 + g];
                const unsigned b1 = vs[(kt * 8 + tig + 4) * 72 + nt * 8 + g];
                MMA(o[0][nt], pa[0], b0, b1);
                MMA(o[1][nt], pa[1], b0, b1);
            }
        }
    }

    // ---- epilogue ----
#pragma unroll
    for (int mi = 0; mi < 2; ++mi)
#pragma unroll
        for (int hf = 0; hf < 2; ++hf) {
            float v = lsum[mi][hf];
            v += __shfl_xor_sync(0xffffffffu, v, 1);
            v += __shfl_xor_sync(0xffffffffu, v, 2);
            lsum[mi][hf] = v;
        }

    __syncthreads();
    float* lsm = (float*)ks;
    if (tig == 0) {
#pragma unroll
        for (int mi = 0; mi < 2; ++mi) {
            lsm[(rbase + mi * 16    ) * 2 + wn] = lsum[mi][0];
            lsm[(rbase + mi * 16 + 8) * 2 + wn] = lsum[mi][1];
        }
    }
    __syncthreads();

    const int bb = bh >> 3, hh = bh & 7;
#pragma unroll
    for (int mi = 0; mi < 2; ++mi) {
        const int iA = rbase + mi * 16;
        const int iB = iA + 8;
        const float ilA = 1.f / (lsm[iA * 2] + lsm[iA * 2 + 1]);
        const float ilB = 1.f / (lsm[iB * 2] + lsm[iB * 2 + 1]);
        float* baseA = g_ao + ((size_t)bb * NSEQ + (i0 + iA)) * DMODEL + hh * DIMH;
        float* baseB = g_ao + ((size_t)bb * NSEQ + (i0 + iB)) * DMODEL + hh * DIMH;
#pragma unroll
        for (int nt = 0; nt < 8; ++nt) {
            const int c = nt * 8 + 2 * tig;
            *(float2*)&baseA[c] = make_float2(
                __uint_as_float(f2tf(o[mi][nt][0] * ilA)),
                __uint_as_float(f2tf(o[mi][nt][1] * ilA)));
            *(float2*)&baseB[c] = make_float2(
                __uint_as_float(f2tf(o[mi][nt][2] * ilB)),
                __uint_as_float(f2tf(o[mi][nt][3] * ilB)));
        }
    }
}

// ============================================================================
// launcher
// ============================================================================
extern "C" void kernel_launch(void* const* d_in, const int* in_sizes, int n_in,
                              void* d_out, int out_size)
{
    const float* x         = (const float*)d_in[0];  // [32,512,512]
    const float* W_qkv     = (const float*)d_in[1];  // [512,1536]
    const float* rel_table = (const float*)d_in[2];  // [1025,64]
    const float* W_out     = (const float*)d_in[3];  // [512,512]
    const float* b_out     = (const float*)d_in[4];  // [512]
    float* out = (float*)d_out;                      // [32,512,512]

    float *xtf, *wqkv, *wout, *relq, *ao;
    cudaGetSymbolAddress((void**)&xtf,  g_xtf);
    cudaGetSymbolAddress((void**)&wqkv, g_wqkv);
    cudaGetSymbolAddress((void**)&wout, g_wout);
    cudaGetSymbolAddress((void**)&relq, g_rel);
    cudaGetSymbolAddress((void**)&ao,   g_ao);

    // 0. pre-convert fp32 -> tf32 bit patterns
    {
        int n4;
        n4 = MROWS * DMODEL / 4;
        cvt_kernel<<<(n4 + 255) / 256, 256>>>((const float4*)x, (float4*)xtf, n4);
        n4 = DMODEL * NQKV / 4;
        cvt_kernel<<<(n4 + 255) / 256, 256>>>((const float4*)W_qkv, (float4*)wqkv, n4);
        n4 = DMODEL * DMODEL / 4;
        cvt_kernel<<<(n4 + 255) / 256, 256>>>((const float4*)W_out, (float4*)wout, n4);
        n4 = 1025 * DIMH / 4;
        cvt_kernel<<<(n4 + 255) / 256, 256>>>((const float4*)rel_table, (float4*)relq, n4);
    }

    // 1. QKV projection
    cudaFuncSetAttribute(mm4_kernel<NQKV, true>,
                         cudaFuncAttributeMaxDynamicSharedMemorySize, MM4_SMEM_BYTES);
    mm4_kernel<NQKV, true><<<dim3(NQKV/128, MROWS/128), 256, MM4_SMEM_BYTES>>>(
        (const unsigned*)xtf, (const unsigned*)wqkv, nullptr, nullptr);

    // 2. fused attention
    cudaFuncSetAttribute(attn5_kernel,
                         cudaFuncAttributeMaxDynamicSharedMemorySize, ATT5_SMEM_BYTES);
    attn5_kernel<<<dim3(BH, NSEQ/64), 128, ATT5_SMEM_BYTES>>>();

    // 3. output projection
    cudaFuncSetAttribute(mm4_kernel<DMODEL, false>,
                         cudaFuncAttributeMaxDynamicSharedMemorySize, MM4_SMEM_BYTES);
    mm4_kernel<DMODEL, false><<<dim3(DMODEL/128, MROWS/128), 256, MM4_SMEM_BYTES>>>(
        (const unsigned*)ao, (const unsigned*)wout, b_out, out);
}

// round 10
// speedup vs baseline: 1.0176x; 1.0176x over previous
#include <cuda_runtime.h>

// Problem constants
#define HEADS   8
#define DIMH    64
#define NSEQ    512
#define BATCH   32
#define DMODEL  512
#define BH      (BATCH*HEADS)        // 256
#define NQKV    (3*HEADS*DIMH)       // 1536
#define MROWS   (BATCH*NSEQ)         // 16384
#define ATT_SCALE 0.125f             // 64^-0.5

// ---------------- scratch (device globals; no cudaMalloc allowed) -----------
// all of these hold tf32-bit-patterns stored as float words
__device__ float g_q   [BH*NSEQ*DIMH];
__device__ float g_k   [BH*NSEQ*DIMH];
__device__ float g_v   [BH*NSEQ*DIMH];
__device__ float g_ao  [BATCH*NSEQ*DMODEL];
__device__ float g_xtf [MROWS*DMODEL];
__device__ float g_wqkv[DMODEL*NQKV];
__device__ float g_wout[DMODEL*DMODEL];
__device__ float g_rel [1025*DIMH];

// ---------------------------------------------------------------------------
// helpers
// ---------------------------------------------------------------------------
__device__ __forceinline__ unsigned f2tf(float x) {
    unsigned r;
    asm("cvt.rna.tf32.f32 %0, %1;" : "=r"(r) : "f"(x));
    return r;
}

__device__ __forceinline__ void mma_tf32_v(float c[4], const unsigned a[4],
                                           unsigned b0, unsigned b1) {
    asm volatile(
        "mma.sync.aligned.m16n8k8.row.col.f32.tf32.tf32.f32 "
        "{%0,%1,%2,%3}, {%4,%5,%6,%7}, {%8,%9}, {%0,%1,%2,%3};\n"
        : "+f"(c[0]), "+f"(c[1]), "+f"(c[2]), "+f"(c[3])
        : "r"(a[0]), "r"(a[1]), "r"(a[2]), "r"(a[3]), "r"(b0), "r"(b1));
}
#define MMA mma_tf32_v

__device__ __forceinline__ void cp16(void* smem_dst, const void* gsrc) {
    unsigned s = (unsigned)__cvta_generic_to_shared(smem_dst);
    asm volatile("cp.async.cg.shared.global [%0], [%1], 16;\n" :: "r"(s), "l"(gsrc));
}
__device__ __forceinline__ void cp_commit() {
    asm volatile("cp.async.commit_group;\n");
}
template<int Nq>
__device__ __forceinline__ void cp_wait() {
    asm volatile("cp.async.wait_group %0;\n" :: "n"(Nq));
}

// ============================================================================
// cvt kernel: fp32 -> tf32 bit pattern (vectorized)
// ============================================================================
__global__ void __launch_bounds__(256) cvt_kernel(const float4* __restrict__ src,
                                                  float4* __restrict__ dst, int n4)
{
    int i = blockIdx.x * 256 + threadIdx.x;
    if (i < n4) {
        float4 v = src[i];
        float4 o;
        o.x = __uint_as_float(f2tf(v.x));
        o.y = __uint_as_float(f2tf(v.y));
        o.z = __uint_as_float(f2tf(v.z));
        o.w = __uint_as_float(f2tf(v.w));
        dst[i] = o;
    }
}

// ============================================================================
// mm5: tf32 GEMM, 128 threads / 4 warps (2m x 2n), 64x64 warp tile (mi=4,ni=8),
// BK=32 k-chunks, 3-stage cp.async ring -> 16 barriers (half of mm3) and
// 128-mma barrier-free compute regions for LDS/mma overlap.
// smem/stage: As 128x36 (4608 w) + Bs 32x136 (4352 w); x3 = 107,520 B.
// ============================================================================
#define MM5_AS_W 4608
#define MM5_BS_W 4352
#define MM5_SMEM_BYTES (3 * (MM5_AS_W + MM5_BS_W) * 4)

template<int N, bool SCATTER>
__global__ void __launch_bounds__(128, 2) mm5_kernel(
    const unsigned* __restrict__ A, const unsigned* __restrict__ B,
    const float* __restrict__ bias, float* __restrict__ Cout)
{
    constexpr int K = 512;
    constexpr int ITERS = 16;          // K / 32
    extern __shared__ unsigned sm[];
    unsigned* AsBase = sm;                      // 3 stages x 4608
    unsigned* BsBase = sm + 3 * MM5_AS_W;       // 3 stages x 4352

    const int tid  = threadIdx.x;
    const int w    = tid >> 5, lane = tid & 31;
    const int g    = lane >> 2, tig = lane & 3;
    const int wm   = w >> 1, wn = w & 1;
    const int bm   = blockIdx.y * 128;
    const int bn   = blockIdx.x * 128;

    // loader indices (128 threads)
    const int ar = tid >> 2;           // 0..31 (+32i)
    const int ac = (tid & 3) << 2;     // 0,4,8,12  (and +16)
    const int br = tid >> 5;           // 0..3  (+4i)
    const int bc = (tid & 31) << 2;    // 0..124

    const unsigned* Ap = A + (size_t)(bm + ar) * K + ac;
    const unsigned* Bp = B + (size_t)br * N + bn + bc;

    auto issue = [&](int it) {
        const int s  = it % 3;
        const int k0 = it * 32;
        unsigned* As = AsBase + s * MM5_AS_W;
        unsigned* Bs = BsBase + s * MM5_BS_W;
#pragma unroll
        for (int i = 0; i < 4; ++i) {
            cp16(&As[(ar + i * 32) * 36 + ac     ], Ap + (size_t)(i * 32) * K + k0);
            cp16(&As[(ar + i * 32) * 36 + ac + 16], Ap + (size_t)(i * 32) * K + k0 + 16);
        }
#pragma unroll
        for (int i = 0; i < 8; ++i)
            cp16(&Bs[(br + i * 4) * 136 + bc], Bp + (size_t)(k0 + i * 4) * N);
    };

    float acc[4][8][4];
#pragma unroll
    for (int mi = 0; mi < 4; ++mi)
#pragma unroll
        for (int ni = 0; ni < 8; ++ni)
#pragma unroll
            for (int e = 0; e < 4; ++e) acc[mi][ni][e] = 0.f;

    // prologue: 2 stages in flight
    issue(0); cp_commit();
    issue(1); cp_commit();

    for (int it = 0; it < ITERS; ++it) {
        const int cur = it % 3;
        cp_wait<1>();                   // stage `it` complete (1 group may pend)
        __syncthreads();                // all warps done with the slot being refilled

        if (it + 2 < ITERS) issue(it + 2);
        cp_commit();                    // exactly one commit per iter

        const unsigned* As = AsBase + cur * MM5_AS_W;
        const unsigned* Bs = BsBase + cur * MM5_BS_W;
#pragma unroll
        for (int kt = 0; kt < 4; ++kt) {
            unsigned af[4][4];
#pragma unroll
            for (int mi = 0; mi < 4; ++mi) {
                const int base = wm * 64 + mi * 16;
                af[mi][0] = As[(base + g    ) * 36 + kt * 8 + tig    ];
                af[mi][1] = As[(base + g + 8) * 36 + kt * 8 + tig    ];
                af[mi][2] = As[(base + g    ) * 36 + kt * 8 + tig + 4];
                af[mi][3] = As[(base + g + 8) * 36 + kt * 8 + tig + 4];
            }
#pragma unroll
            for (int ni = 0; ni < 8; ++ni) {
                const unsigned b0 = Bs[(kt * 8 + tig    ) * 136 + wn * 64 + ni * 8 + g];
                const unsigned b1 = Bs[(kt * 8 + tig + 4) * 136 + wn * 64 + ni * 8 + g];
#pragma unroll
                for (int mi = 0; mi < 4; ++mi)
                    MMA(acc[mi][ni], af[mi], b0, b1);
            }
        }
    }

    // ---- epilogue ----
    if (SCATTER) {
        const int which = bn >> 9;
        float* dst = (which == 0) ? g_q : (which == 1) ? g_k : g_v;
#pragma unroll
        for (int mi = 0; mi < 4; ++mi) {
            const int r0  = bm + wm * 64 + mi * 16 + g;
            const int bb  = r0 >> 9;
            const int nn0 = r0 & 511;
#pragma unroll
            for (int ni = 0; ni < 8; ++ni) {
                const int c  = bn + wn * 64 + ni * 8 + 2 * tig;
                const int h  = (c & 511) >> 6;
                const int dd = c & 63;
                const size_t rowbase = (size_t)((bb << 3) + h) * NSEQ;
                *(float2*)&dst[(rowbase + nn0    ) * DIMH + dd] = make_float2(
                    __uint_as_float(f2tf(acc[mi][ni][0])),
                    __uint_as_float(f2tf(acc[mi][ni][1])));
                *(float2*)&dst[(rowbase + nn0 + 8) * DIMH + dd] = make_float2(
                    __uint_as_float(f2tf(acc[mi][ni][2])),
                    __uint_as_float(f2tf(acc[mi][ni][3])));
            }
        }
    } else {
#pragma unroll
        for (int mi = 0; mi < 4; ++mi) {
            const int r = bm + wm * 64 + mi * 16 + g;
#pragma unroll
            for (int ni = 0; ni < 8; ++ni) {
                const int c = bn + wn * 64 + ni * 8 + 2 * tig;
                const float2 bv = *(const float2*)&bias[c];
                *(float2*)&Cout[(size_t)r * N + c] =
                    make_float2(acc[mi][ni][0] + bv.x, acc[mi][ni][1] + bv.y);
                *(float2*)&Cout[(size_t)(r + 8) * N + c] =
                    make_float2(acc[mi][ni][2] + bv.x, acc[mi][ni][3] + bv.y);
            }
        }
    }
}

// ============================================================================
// attn5: unchanged from R8 (passing).
// ============================================================================
#define ATT5_SMEM_WORDS (4352 + 4352 + 9216 + 8448)
#define ATT5_SMEM_BYTES (ATT5_SMEM_WORDS * 4)

__global__ void __launch_bounds__(128, 2) attn5_kernel()
{
    extern __shared__ unsigned smu[];
    unsigned* rels   = smu;                    // 64 x 68 (Q staging alias)
    unsigned* ks     = smu + 4352;             // 64 x 68 (l-exchange alias)
    unsigned* vsbuf  = smu + 8704;             // 2 x 64 x 72
    float*    pbs    = (float*)(smu + 17920);  // 64 x 132
    unsigned* ps     = (unsigned*)pbs;

    const int tid  = threadIdx.x;
    const int w    = tid >> 5;
    const int lane = tid & 31;
    const int g    = lane >> 2;
    const int tig  = lane & 3;
    const int wm   = w >> 1, wn = w & 1;

    const int bh = blockIdx.x;
    const int qb = blockIdx.y;
    const int i0 = qb * 64;
    const int rbase = wm * 32 + g;

    const unsigned* qg = (const unsigned*)g_q + ((size_t)bh * NSEQ + i0) * DIMH;
    const unsigned* kg = (const unsigned*)g_k + (size_t)bh * NSEQ * DIMH;
    const unsigned* vg = (const unsigned*)g_v + (size_t)bh * NSEQ * DIMH;
    const unsigned* rg = (const unsigned*)g_rel;

    auto copy_tile = [&](unsigned* dst, const unsigned* src, int st) {
#pragma unroll
        for (int k = 0; k < 8; ++k) {
            const int c  = tid + k * 128;      // chunk 0..1023
            const int r  = c >> 4;             // row 0..63
            const int wo = (c & 15) << 2;      // word offset 0..60
            cp16(&dst[r * st + wo], src + r * DIMH + wo);
        }
    };

    auto issue_tiles = [&](int t) {
        const int j0 = t * 64;
        copy_tile(ks, kg + (size_t)j0 * DIMH, 68);
        copy_tile(vsbuf + (t & 1) * 4608, vg + (size_t)j0 * DIMH, 72);
        copy_tile(rels, rg + (size_t)(i0 + 449 - j0) * DIMH, 68);
    };

    // ---- stage Q into rels via cp.async ----
    copy_tile(rels, qg, 68);
    cp_commit();
    cp_wait<0>();
    __syncthreads();

    // ---- extract Q A-fragments ----
    unsigned qa[2][8][4];
#pragma unroll
    for (int mi = 0; mi < 2; ++mi) {
        const int r0 = rbase + mi * 16;
#pragma unroll
        for (int kt = 0; kt < 8; ++kt) {
            const int c = kt * 8 + tig;
            qa[mi][kt][0] = rels[ r0      * 68 + c    ];
            qa[mi][kt][1] = rels[(r0 + 8) * 68 + c    ];
            qa[mi][kt][2] = rels[ r0      * 68 + c + 4];
            qa[mi][kt][3] = rels[(r0 + 8) * 68 + c + 4];
        }
    }
    __syncthreads();   // rels free

    // ---- prologue: rel chunk(-1) -> pbs half 1 ----
    {
        copy_tile(rels, rg + (size_t)(i0 + 513) * DIMH, 68);
        cp_commit();
        cp_wait<0>();
        __syncthreads();
#pragma unroll
        for (int nt = 0; nt < 4; ++nt) {
            float a0[4] = {0.f,0.f,0.f,0.f}, a1[4] = {0.f,0.f,0.f,0.f};
            const int dr = wn * 32 + nt * 8 + g;
#pragma unroll
            for (int kt = 0; kt < 8; ++kt) {
                const unsigned b0 = rels[dr * 68 + kt * 8 + tig    ];
                const unsigned b1 = rels[dr * 68 + kt * 8 + tig + 4];
                MMA(a0, qa[0][kt], b0, b1);
                MMA(a1, qa[1][kt], b0, b1);
            }
            const int col = 64 + wn * 32 + nt * 8 + 2 * tig;
            *(float2*)&pbs[(rbase     ) * 132 + col] = make_float2(a0[0], a0[1]);
            *(float2*)&pbs[(rbase +  8) * 132 + col] = make_float2(a0[2], a0[3]);
            *(float2*)&pbs[(rbase + 16) * 132 + col] = make_float2(a1[0], a1[1]);
            *(float2*)&pbs[(rbase + 24) * 132 + col] = make_float2(a1[2], a1[3]);
        }
    }
    __syncthreads();

    issue_tiles(0);
    cp_commit();

    float lsum[2][2] = {{0.f, 0.f}, {0.f, 0.f}};
    float o[2][8][4];
#pragma unroll
    for (int mi = 0; mi < 2; ++mi)
#pragma unroll
        for (int nt = 0; nt < 8; ++nt)
#pragma unroll
            for (int e = 0; e < 4; ++e) o[mi][nt][e] = 0.f;

    for (int t = 0; t < 8; ++t) {
        const int h = t & 1;
        const unsigned* vs = vsbuf + h * 4608;

        cp_wait<0>();
        __syncthreads();               // tiles t ready; all warps past PV(t-1)

        // ---- PB new chunk -> pbs half h ----
#pragma unroll
        for (int nt = 0; nt < 4; ++nt) {
            float a0[4] = {0.f,0.f,0.f,0.f}, a1[4] = {0.f,0.f,0.f,0.f};
            const int dr = wn * 32 + nt * 8 + g;
#pragma unroll
            for (int kt = 0; kt < 8; ++kt) {
                const unsigned b0 = rels[dr * 68 + kt * 8 + tig    ];
                const unsigned b1 = rels[dr * 68 + kt * 8 + tig + 4];
                MMA(a0, qa[0][kt], b0, b1);
                MMA(a1, qa[1][kt], b0, b1);
            }
            const int col = h * 64 + wn * 32 + nt * 8 + 2 * tig;
            *(float2*)&pbs[(rbase     ) * 132 + col] = make_float2(a0[0], a0[1]);
            *(float2*)&pbs[(rbase +  8) * 132 + col] = make_float2(a0[2], a0[3]);
            *(float2*)&pbs[(rbase + 16) * 132 + col] = make_float2(a1[0], a1[1]);
            *(float2*)&pbs[(rbase + 24) * 132 + col] = make_float2(a1[2], a1[3]);
        }

        // ---- QK ----
        float s[2][4][4];
#pragma unroll
        for (int nt = 0; nt < 4; ++nt) {
            const int jr = wn * 32 + nt * 8 + g;
#pragma unroll
            for (int mi = 0; mi < 2; ++mi)
                s[mi][nt][0] = s[mi][nt][1] = s[mi][nt][2] = s[mi][nt][3] = 0.f;
#pragma unroll
            for (int kt = 0; kt < 8; ++kt) {
                const unsigned b0 = ks[jr * 68 + kt * 8 + tig    ];
                const unsigned b1 = ks[jr * 68 + kt * 8 + tig + 4];
                MMA(s[0][nt], qa[0][kt], b0, b1);
                MMA(s[1][nt], qa[1][kt], b0, b1);
            }
        }
        __syncthreads();               // pbs chunk visible; ks/rels free

        // ---- bias gather + exp (no max) + partial sums ----
#pragma unroll
        for (int mi = 0; mi < 2; ++mi) {
            const int iA = rbase + mi * 16;
            const int iB = iA + 8;
#pragma unroll
            for (int nt = 0; nt < 4; ++nt) {
                const int jj = wn * 32 + nt * 8 + 2 * tig;
                const int oA0 = iA - jj + 63, oA1 = oA0 - 1;
                const int oB0 = iB - jj + 63, oB1 = oB0 - 1;
                const int pA0 = ((h ^ (oA0 >> 6)) << 6) | (oA0 & 63);
                const int pA1 = ((h ^ (oA1 >> 6)) << 6) | (oA1 & 63);
                const int pB0 = ((h ^ (oB0 >> 6)) << 6) | (oB0 & 63);
                const int pB1 = ((h ^ (oB1 >> 6)) << 6) | (oB1 & 63);
                float e0 = __expf((s[mi][nt][0] + pbs[iA * 132 + pA0]) * ATT_SCALE);
                float e1 = __expf((s[mi][nt][1] + pbs[iA * 132 + pA1]) * ATT_SCALE);
                float e2 = __expf((s[mi][nt][2] + pbs[iB * 132 + pB0]) * ATT_SCALE);
                float e3 = __expf((s[mi][nt][3] + pbs[iB * 132 + pB1]) * ATT_SCALE);
                s[mi][nt][0] = e0; s[mi][nt][1] = e1;
                s[mi][nt][2] = e2; s[mi][nt][3] = e3;
                lsum[mi][0] += e0 + e1;
                lsum[mi][1] += e2 + e3;
            }
        }
        __syncthreads();               // gathers done before P overwrite

        // ---- write P (tf32) into the dead half (h^1) ----
        const int pc0 = (h ^ 1) * 64;
#pragma unroll
        for (int mi = 0; mi < 2; ++mi) {
            const int iA = rbase + mi * 16;
            const int iB = iA + 8;
#pragma unroll
            for (int nt = 0; nt < 4; ++nt) {
                const int c = pc0 + wn * 32 + nt * 8 + 2 * tig;
                ps[iA * 132 + c    ] = f2tf(s[mi][nt][0]);
                ps[iA * 132 + c + 1] = f2tf(s[mi][nt][1]);
                ps[iB * 132 + c    ] = f2tf(s[mi][nt][2]);
                ps[iB * 132 + c + 1] = f2tf(s[mi][nt][3]);
            }
        }
        __syncthreads();               // P visible

        if (t + 1 < 8) issue_tiles(t + 1);
        cp_commit();

#pragma unroll
        for (int kt = 0; kt < 8; ++kt) {
            unsigned pa[2][4];
#pragma unroll
            for (int mi = 0; mi < 2; ++mi) {
                const int iA = rbase + mi * 16;
                const int iB = iA + 8;
                pa[mi][0] = ps[iA * 132 + pc0 + kt * 8 + tig    ];
                pa[mi][1] = ps[iB * 132 + pc0 + kt * 8 + tig    ];
                pa[mi][2] = ps[iA * 132 + pc0 + kt * 8 + tig + 4];
                pa[mi][3] = ps[iB * 132 + pc0 + kt * 8 + tig + 4];
            }
#pragma unroll
            for (int nt = 0; nt < 8; ++nt) {
                const unsigned b0 = vs[(kt * 8 + tig    ) * 72 + nt * 8 + g];
                const unsigned b1 = vs[(kt * 8 + tig + 4) * 72 + nt * 8 + g];
                MMA(o[0][nt], pa[0], b0, b1);
                MMA(o[1][nt], pa[1], b0, b1);
            }
        }
    }

    // ---- epilogue ----
#pragma unroll
    for (int mi = 0; mi < 2; ++mi)
#pragma unroll
        for (int hf = 0; hf < 2; ++hf) {
            float v = lsum[mi][hf];
            v += __shfl_xor_sync(0xffffffffu, v, 1);
            v += __shfl_xor_sync(0xffffffffu, v, 2);
            lsum[mi][hf] = v;
        }

    __syncthreads();
    float* lsm = (float*)ks;
    if (tig == 0) {
#pragma unroll
        for (int mi = 0; mi < 2; ++mi) {
            lsm[(rbase + mi * 16    ) * 2 + wn] = lsum[mi][0];
            lsm[(rbase + mi * 16 + 8) * 2 + wn] = lsum[mi][1];
        }
    }
    __syncthreads();

    const int bb = bh >> 3, hh = bh & 7;
#pragma unroll
    for (int mi = 0; mi < 2; ++mi) {
        const int iA = rbase + mi * 16;
        const int iB = iA + 8;
        const float ilA = 1.f / (lsm[iA * 2] + lsm[iA * 2 + 1]);
        const float ilB = 1.f / (lsm[iB * 2] + lsm[iB * 2 + 1]);
        float* baseA = g_ao + ((size_t)bb * NSEQ + (i0 + iA)) * DMODEL + hh * DIMH;
        float* baseB = g_ao + ((size_t)bb * NSEQ + (i0 + iB)) * DMODEL + hh * DIMH;
#pragma unroll
        for (int nt = 0; nt < 8; ++nt) {
            const int c = nt * 8 + 2 * tig;
            *(float2*)&baseA[c] = make_float2(
                __uint_as_float(f2tf(o[mi][nt][0] * ilA)),
                __uint_as_float(f2tf(o[mi][nt][1] * ilA)));
            *(float2*)&baseB[c] = make_float2(
                __uint_as_float(f2tf(o[mi][nt][2] * ilB)),
                __uint_as_float(f2tf(o[mi][nt][3] * ilB)));
        }
    }
}

// ============================================================================
// launcher
// ============================================================================
extern "C" void kernel_launch(void* const* d_in, const int* in_sizes, int n_in,
                              void* d_out, int out_size)
{
    const float* x         = (const float*)d_in[0];  // [32,512,512]
    const float* W_qkv     = (const float*)d_in[1];  // [512,1536]
    const float* rel_table = (const float*)d_in[2];  // [1025,64]
    const float* W_out     = (const float*)d_in[3];  // [512,512]
    const float* b_out     = (const float*)d_in[4];  // [512]
    float* out = (float*)d_out;                      // [32,512,512]

    float *xtf, *wqkv, *wout, *relq, *ao;
    cudaGetSymbolAddress((void**)&xtf,  g_xtf);
    cudaGetSymbolAddress((void**)&wqkv, g_wqkv);
    cudaGetSymbolAddress((void**)&wout, g_wout);
    cudaGetSymbolAddress((void**)&relq, g_rel);
    cudaGetSymbolAddress((void**)&ao,   g_ao);

    // 0. pre-convert fp32 -> tf32 bit patterns
    {
        int n4;
        n4 = MROWS * DMODEL / 4;
        cvt_kernel<<<(n4 + 255) / 256, 256>>>((const float4*)x, (float4*)xtf, n4);
        n4 = DMODEL * NQKV / 4;
        cvt_kernel<<<(n4 + 255) / 256, 256>>>((const float4*)W_qkv, (float4*)wqkv, n4);
        n4 = DMODEL * DMODEL / 4;
        cvt_kernel<<<(n4 + 255) / 256, 256>>>((const float4*)W_out, (float4*)wout, n4);
        n4 = 1025 * DIMH / 4;
        cvt_kernel<<<(n4 + 255) / 256, 256>>>((const float4*)rel_table, (float4*)relq, n4);
    }

    // 1. QKV projection
    cudaFuncSetAttribute(mm5_kernel<NQKV, true>,
                         cudaFuncAttributeMaxDynamicSharedMemorySize, MM5_SMEM_BYTES);
    mm5_kernel<NQKV, true><<<dim3(NQKV/128, MROWS/128), 128, MM5_SMEM_BYTES>>>(
        (const unsigned*)xtf, (const unsigned*)wqkv, nullptr, nullptr);

    // 2. fused attention
    cudaFuncSetAttribute(attn5_kernel,
                         cudaFuncAttributeMaxDynamicSharedMemorySize, ATT5_SMEM_BYTES);
    attn5_kernel<<<dim3(BH, NSEQ/64), 128, ATT5_SMEM_BYTES>>>();

    // 3. output projection
    cudaFuncSetAttribute(mm5_kernel<DMODEL, false>,
                         cudaFuncAttributeMaxDynamicSharedMemorySize, MM5_SMEM_BYTES);
    mm5_kernel<DMODEL, false><<<dim3(DMODEL/128, MROWS/128), 128, MM5_SMEM_BYTES>>>(
        (const unsigned*)ao, (const unsigned*)wout, b_out, out);
}

// round 12
// speedup vs baseline: 1.0261x; 1.0084x over previous
#include <cuda_runtime.h>

// Problem constants
#define HEADS   8
#define DIMH    64
#define NSEQ    512
#define BATCH   32
#define DMODEL  512
#define BH      (BATCH*HEADS)        // 256
#define NQKV    (3*HEADS*DIMH)       // 1536
#define MROWS   (BATCH*NSEQ)         // 16384
#define ATT_SCALE 0.125f             // 64^-0.5

// ---------------- scratch (device globals; no cudaMalloc allowed) -----------
// all of these hold tf32-bit-patterns stored as float words
__device__ float g_q   [BH*NSEQ*DIMH];
__device__ float g_k   [BH*NSEQ*DIMH];
__device__ float g_v   [BH*NSEQ*DIMH];
__device__ float g_ao  [BATCH*NSEQ*DMODEL];
__device__ float g_xtf [MROWS*DMODEL];
__device__ float g_wqkv[DMODEL*NQKV];
__device__ float g_wout[DMODEL*DMODEL];
__device__ float g_rel [1025*DIMH];

// ---------------------------------------------------------------------------
// helpers
// ---------------------------------------------------------------------------
__device__ __forceinline__ unsigned f2tf(float x) {
    unsigned r;
    asm("cvt.rna.tf32.f32 %0, %1;" : "=r"(r) : "f"(x));
    return r;
}

__device__ __forceinline__ void mma_tf32_v(float c[4], const unsigned a[4],
                                           unsigned b0, unsigned b1) {
    asm volatile(
        "mma.sync.aligned.m16n8k8.row.col.f32.tf32.tf32.f32 "
        "{%0,%1,%2,%3}, {%4,%5,%6,%7}, {%8,%9}, {%0,%1,%2,%3};\n"
        : "+f"(c[0]), "+f"(c[1]), "+f"(c[2]), "+f"(c[3])
        : "r"(a[0]), "r"(a[1]), "r"(a[2]), "r"(a[3]), "r"(b0), "r"(b1));
}
#define MMA mma_tf32_v

__device__ __forceinline__ void cp16(void* smem_dst, const void* gsrc) {
    unsigned s = (unsigned)__cvta_generic_to_shared(smem_dst);
    asm volatile("cp.async.cg.shared.global [%0], [%1], 16;\n" :: "r"(s), "l"(gsrc));
}
__device__ __forceinline__ void cp_commit() {
    asm volatile("cp.async.commit_group;\n");
}
template<int Nq>
__device__ __forceinline__ void cp_wait() {
    asm volatile("cp.async.wait_group %0;\n" :: "n"(Nq));
}
__device__ __forceinline__ void bar_pair(int id) {   // 64-thread named barrier
    asm volatile("bar.sync %0, 64;" :: "r"(id) : "memory");
}

// ============================================================================
// cvt kernel: fp32 -> tf32 bit pattern (vectorized)
// ============================================================================
__global__ void __launch_bounds__(256) cvt_kernel(const float4* __restrict__ src,
                                                  float4* __restrict__ dst, int n4)
{
    int i = blockIdx.x * 256 + threadIdx.x;
    if (i < n4) {
        float4 v = src[i];
        float4 o;
        o.x = __uint_as_float(f2tf(v.x));
        o.y = __uint_as_float(f2tf(v.y));
        o.z = __uint_as_float(f2tf(v.z));
        o.w = __uint_as_float(f2tf(v.w));
        dst[i] = o;
    }
}

// ============================================================================
// mm5: tf32 GEMM, 128 threads / 4 warps (2m x 2n), 64x64 warp tile (mi=4,ni=8),
// BK=32 k-chunks, 3-stage cp.async ring (unchanged from R10 — at mma ceiling).
// ============================================================================
#define MM5_AS_W 4608
#define MM5_BS_W 4352
#define MM5_SMEM_BYTES (3 * (MM5_AS_W + MM5_BS_W) * 4)

template<int N, bool SCATTER>
__global__ void __launch_bounds__(128, 2) mm5_kernel(
    const unsigned* __restrict__ A, const unsigned* __restrict__ B,
    const float* __restrict__ bias, float* __restrict__ Cout)
{
    constexpr int K = 512;
    constexpr int ITERS = 16;          // K / 32
    extern __shared__ unsigned sm[];
    unsigned* AsBase = sm;                      // 3 stages x 4608
    unsigned* BsBase = sm + 3 * MM5_AS_W;       // 3 stages x 4352

    const int tid  = threadIdx.x;
    const int w    = tid >> 5, lane = tid & 31;
    const int g    = lane >> 2, tig = lane & 3;
    const int wm   = w >> 1, wn = w & 1;
    const int bm   = blockIdx.y * 128;
    const int bn   = blockIdx.x * 128;

    const int ar = tid >> 2;
    const int ac = (tid & 3) << 2;
    const int br = tid >> 5;
    const int bc = (tid & 31) << 2;

    const unsigned* Ap = A + (size_t)(bm + ar) * K + ac;
    const unsigned* Bp = B + (size_t)br * N + bn + bc;

    auto issue = [&](int it) {
        const int s  = it % 3;
        const int k0 = it * 32;
        unsigned* As = AsBase + s * MM5_AS_W;
        unsigned* Bs = BsBase + s * MM5_BS_W;
#pragma unroll
        for (int i = 0; i < 4; ++i) {
            cp16(&As[(ar + i * 32) * 36 + ac     ], Ap + (size_t)(i * 32) * K + k0);
            cp16(&As[(ar + i * 32) * 36 + ac + 16], Ap + (size_t)(i * 32) * K + k0 + 16);
        }
#pragma unroll
        for (int i = 0; i < 8; ++i)
            cp16(&Bs[(br + i * 4) * 136 + bc], Bp + (size_t)(k0 + i * 4) * N);
    };

    float acc[4][8][4];
#pragma unroll
    for (int mi = 0; mi < 4; ++mi)
#pragma unroll
        for (int ni = 0; ni < 8; ++ni)
#pragma unroll
            for (int e = 0; e < 4; ++e) acc[mi][ni][e] = 0.f;

    issue(0); cp_commit();
    issue(1); cp_commit();

    for (int it = 0; it < ITERS; ++it) {
        const int cur = it % 3;
        cp_wait<1>();
        __syncthreads();

        if (it + 2 < ITERS) issue(it + 2);
        cp_commit();

        const unsigned* As = AsBase + cur * MM5_AS_W;
        const unsigned* Bs = BsBase + cur * MM5_BS_W;
#pragma unroll
        for (int kt = 0; kt < 4; ++kt) {
            unsigned af[4][4];
#pragma unroll
            for (int mi = 0; mi < 4; ++mi) {
                const int base = wm * 64 + mi * 16;
                af[mi][0] = As[(base + g    ) * 36 + kt * 8 + tig    ];
                af[mi][1] = As[(base + g + 8) * 36 + kt * 8 + tig    ];
                af[mi][2] = As[(base + g    ) * 36 + kt * 8 + tig + 4];
                af[mi][3] = As[(base + g + 8) * 36 + kt * 8 + tig + 4];
            }
#pragma unroll
            for (int ni = 0; ni < 8; ++ni) {
                const unsigned b0 = Bs[(kt * 8 + tig    ) * 136 + wn * 64 + ni * 8 + g];
                const unsigned b1 = Bs[(kt * 8 + tig + 4) * 136 + wn * 64 + ni * 8 + g];
#pragma unroll
                for (int mi = 0; mi < 4; ++mi)
                    MMA(acc[mi][ni], af[mi], b0, b1);
            }
        }
    }

    if (SCATTER) {
        const int which = bn >> 9;
        float* dst = (which == 0) ? g_q : (which == 1) ? g_k : g_v;
#pragma unroll
        for (int mi = 0; mi < 4; ++mi) {
            const int r0  = bm + wm * 64 + mi * 16 + g;
            const int bb  = r0 >> 9;
            const int nn0 = r0 & 511;
#pragma unroll
            for (int ni = 0; ni < 8; ++ni) {
                const int c  = bn + wn * 64 + ni * 8 + 2 * tig;
                const int h  = (c & 511) >> 6;
                const int dd = c & 63;
                const size_t rowbase = (size_t)((bb << 3) + h) * NSEQ;
                *(float2*)&dst[(rowbase + nn0    ) * DIMH + dd] = make_float2(
                    __uint_as_float(f2tf(acc[mi][ni][0])),
                    __uint_as_float(f2tf(acc[mi][ni][1])));
                *(float2*)&dst[(rowbase + nn0 + 8) * DIMH + dd] = make_float2(
                    __uint_as_float(f2tf(acc[mi][ni][2])),
                    __uint_as_float(f2tf(acc[mi][ni][3])));
            }
        }
    } else {
#pragma unroll
        for (int mi = 0; mi < 4; ++mi) {
            const int r = bm + wm * 64 + mi * 16 + g;
#pragma unroll
            for (int ni = 0; ni < 8; ++ni) {
                const int c = bn + wn * 64 + ni * 8 + 2 * tig;
                const float2 bv = *(const float2*)&bias[c];
                *(float2*)&Cout[(size_t)r * N + c] =
                    make_float2(acc[mi][ni][0] + bv.x, acc[mi][ni][1] + bv.y);
                *(float2*)&Cout[(size_t)(r + 8) * N + c] =
                    make_float2(acc[mi][ni][2] + bv.x, acc[mi][ni][3] + bv.y);
            }
        }
    }
}

// ============================================================================
// attn6: R10's attn5 with two latency fixes:
//  (1) next-iter tile loads issued right after S3 (ks/rels provably free)
//      so cp.async overlaps gather+exp+P-write+PV, not just PV;
//  (2) S4/S5 demoted to pair-local named barriers (bar.sync wm+1, 64) —
//      gather->P-overwrite->PV deps are confined to a wm-pair's 32 rows.
// ============================================================================
#define ATT6_SMEM_WORDS (4352 + 4352 + 9216 + 8448)
#define ATT6_SMEM_BYTES (ATT6_SMEM_WORDS * 4)

__global__ void __launch_bounds__(128, 2) attn6_kernel()
{
    extern __shared__ unsigned smu[];
    unsigned* rels   = smu;                    // 64 x 68 (Q staging alias)
    unsigned* ks     = smu + 4352;             // 64 x 68 (l-exchange alias)
    unsigned* vsbuf  = smu + 8704;             // 2 x 64 x 72
    float*    pbs    = (float*)(smu + 17920);  // 64 x 132
    unsigned* ps     = (unsigned*)pbs;

    const int tid  = threadIdx.x;
    const int w    = tid >> 5;
    const int lane = tid & 31;
    const int g    = lane >> 2;
    const int tig  = lane & 3;
    const int wm   = w >> 1, wn = w & 1;

    const int bh = blockIdx.x;
    const int qb = blockIdx.y;
    const int i0 = qb * 64;
    const int rbase = wm * 32 + g;
    const int pbar  = wm + 1;                  // named barrier id for this pair

    const unsigned* qg = (const unsigned*)g_q + ((size_t)bh * NSEQ + i0) * DIMH;
    const unsigned* kg = (const unsigned*)g_k + (size_t)bh * NSEQ * DIMH;
    const unsigned* vg = (const unsigned*)g_v + (size_t)bh * NSEQ * DIMH;
    const unsigned* rg = (const unsigned*)g_rel;

    auto copy_tile = [&](unsigned* dst, const unsigned* src, int st) {
#pragma unroll
        for (int k = 0; k < 8; ++k) {
            const int c  = tid + k * 128;
            const int r  = c >> 4;
            const int wo = (c & 15) << 2;
            cp16(&dst[r * st + wo], src + r * DIMH + wo);
        }
    };

    auto issue_tiles = [&](int t) {
        const int j0 = t * 64;
        copy_tile(ks, kg + (size_t)j0 * DIMH, 68);
        copy_tile(vsbuf + (t & 1) * 4608, vg + (size_t)j0 * DIMH, 72);
        copy_tile(rels, rg + (size_t)(i0 + 449 - j0) * DIMH, 68);
    };

    // ---- stage Q into rels via cp.async ----
    copy_tile(rels, qg, 68);
    cp_commit();
    cp_wait<0>();
    __syncthreads();

    // ---- extract Q A-fragments ----
    unsigned qa[2][8][4];
#pragma unroll
    for (int mi = 0; mi < 2; ++mi) {
        const int r0 = rbase + mi * 16;
#pragma unroll
        for (int kt = 0; kt < 8; ++kt) {
            const int c = kt * 8 + tig;
            qa[mi][kt][0] = rels[ r0      * 68 + c    ];
            qa[mi][kt][1] = rels[(r0 + 8) * 68 + c    ];
            qa[mi][kt][2] = rels[ r0      * 68 + c + 4];
            qa[mi][kt][3] = rels[(r0 + 8) * 68 + c + 4];
        }
    }
    __syncthreads();   // rels free

    // ---- prologue: rel chunk(-1) -> pbs half 1 ----
    {
        copy_tile(rels, rg + (size_t)(i0 + 513) * DIMH, 68);
        cp_commit();
        cp_wait<0>();
        __syncthreads();
#pragma unroll
        for (int nt = 0; nt < 4; ++nt) {
            float a0[4] = {0.f,0.f,0.f,0.f}, a1[4] = {0.f,0.f,0.f,0.f};
            const int dr = wn * 32 + nt * 8 + g;
#pragma unroll
            for (int kt = 0; kt < 8; ++kt) {
                const unsigned b0 = rels[dr * 68 + kt * 8 + tig    ];
                const unsigned b1 = rels[dr * 68 + kt * 8 + tig + 4];
                MMA(a0, qa[0][kt], b0, b1);
                MMA(a1, qa[1][kt], b0, b1);
            }
            const int col = 64 + wn * 32 + nt * 8 + 2 * tig;
            *(float2*)&pbs[(rbase     ) * 132 + col] = make_float2(a0[0], a0[1]);
            *(float2*)&pbs[(rbase +  8) * 132 + col] = make_float2(a0[2], a0[3]);
            *(float2*)&pbs[(rbase + 16) * 132 + col] = make_float2(a1[0], a1[1]);
            *(float2*)&pbs[(rbase + 24) * 132 + col] = make_float2(a1[2], a1[3]);
        }
    }
    __syncthreads();       // all warps done reading rels before t=0 tiles land

    issue_tiles(0);
    cp_commit();

    float lsum[2][2] = {{0.f, 0.f}, {0.f, 0.f}};
    float o[2][8][4];
#pragma unroll
    for (int mi = 0; mi < 2; ++mi)
#pragma unroll
        for (int nt = 0; nt < 8; ++nt)
#pragma unroll
            for (int e = 0; e < 4; ++e) o[mi][nt][e] = 0.f;

    for (int t = 0; t < 8; ++t) {
        const int h = t & 1;
        const unsigned* vs = vsbuf + h * 4608;

        cp_wait<0>();
        __syncthreads();               // S2: tiles t ready; all warps past PV(t-1)

        // ---- PB new chunk -> pbs half h ----
#pragma unroll
        for (int nt = 0; nt < 4; ++nt) {
            float a0[4] = {0.f,0.f,0.f,0.f}, a1[4] = {0.f,0.f,0.f,0.f};
            const int dr = wn * 32 + nt * 8 + g;
#pragma unroll
            for (int kt = 0; kt < 8; ++kt) {
                const unsigned b0 = rels[dr * 68 + kt * 8 + tig    ];
                const unsigned b1 = rels[dr * 68 + kt * 8 + tig + 4];
                MMA(a0, qa[0][kt], b0, b1);
                MMA(a1, qa[1][kt], b0, b1);
            }
            const int col = h * 64 + wn * 32 + nt * 8 + 2 * tig;
            *(float2*)&pbs[(rbase     ) * 132 + col] = make_float2(a0[0], a0[1]);
            *(float2*)&pbs[(rbase +  8) * 132 + col] = make_float2(a0[2], a0[3]);
            *(float2*)&pbs[(rbase + 16) * 132 + col] = make_float2(a1[0], a1[1]);
            *(float2*)&pbs[(rbase + 24) * 132 + col] = make_float2(a1[2], a1[3]);
        }

        // ---- QK ----
        float s[2][4][4];
#pragma unroll
        for (int nt = 0; nt < 4; ++nt) {
            const int jr = wn * 32 + nt * 8 + g;
#pragma unroll
            for (int mi = 0; mi < 2; ++mi)
                s[mi][nt][0] = s[mi][nt][1] = s[mi][nt][2] = s[mi][nt][3] = 0.f;
#pragma unroll
            for (int kt = 0; kt < 8; ++kt) {
                const unsigned b0 = ks[jr * 68 + kt * 8 + tig    ];
                const unsigned b1 = ks[jr * 68 + kt * 8 + tig + 4];
                MMA(s[0][nt], qa[0][kt], b0, b1);
                MMA(s[1][nt], qa[1][kt], b0, b1);
            }
        }
        __syncthreads();               // S3 (CTA): pbs chunk visible; ks/rels free

        // ---- issue next tiles NOW: overlaps gather+exp+P-write+PV ----
        if (t + 1 < 8) issue_tiles(t + 1);
        cp_commit();

        // ---- bias gather + exp (no max) + partial sums ----
#pragma unroll
        for (int mi = 0; mi < 2; ++mi) {
            const int iA = rbase + mi * 16;
            const int iB = iA + 8;
#pragma unroll
            for (int nt = 0; nt < 4; ++nt) {
                const int jj = wn * 32 + nt * 8 + 2 * tig;
                const int oA0 = iA - jj + 63, oA1 = oA0 - 1;
                const int oB0 = iB - jj + 63, oB1 = oB0 - 1;
                const int pA0 = ((h ^ (oA0 >> 6)) << 6) | (oA0 & 63);
                const int pA1 = ((h ^ (oA1 >> 6)) << 6) | (oA1 & 63);
                const int pB0 = ((h ^ (oB0 >> 6)) << 6) | (oB0 & 63);
                const int pB1 = ((h ^ (oB1 >> 6)) << 6) | (oB1 & 63);
                float e0 = __expf((s[mi][nt][0] + pbs[iA * 132 + pA0]) * ATT_SCALE);
                float e1 = __expf((s[mi][nt][1] + pbs[iA * 132 + pA1]) * ATT_SCALE);
                float e2 = __expf((s[mi][nt][2] + pbs[iB * 132 + pB0]) * ATT_SCALE);
                float e3 = __expf((s[mi][nt][3] + pbs[iB * 132 + pB1]) * ATT_SCALE);
                s[mi][nt][0] = e0; s[mi][nt][1] = e1;
                s[mi][nt][2] = e2; s[mi][nt][3] = e3;
                lsum[mi][0] += e0 + e1;
                lsum[mi][1] += e2 + e3;
            }
        }
        bar_pair(pbar);                // S4 (pair): own pair's gathers done

        // ---- write P (tf32) into the dead half (h^1) ----
        const int pc0 = (h ^ 1) * 64;
#pragma unroll
        for (int mi = 0; mi < 2; ++mi) {
            const int iA = rbase + mi * 16;
            const int iB = iA + 8;
#pragma unroll
            for (int nt = 0; nt < 4; ++nt) {
                const int c = pc0 + wn * 32 + nt * 8 + 2 * tig;
                ps[iA * 132 + c    ] = f2tf(s[mi][nt][0]);
                ps[iA * 132 + c + 1] = f2tf(s[mi][nt][1]);
                ps[iB * 132 + c    ] = f2tf(s[mi][nt][2]);
                ps[iB * 132 + c + 1] = f2tf(s[mi][nt][3]);
            }
        }
        bar_pair(pbar);                // S5 (pair): own pair's P rows visible

        // ---- O += P @ V ----
#pragma unroll
        for (int kt = 0; kt < 8; ++kt) {
            unsigned pa[2][4];
#pragma unroll
            for (int mi = 0; mi < 2; ++mi) {
                const int iA = rbase + mi * 16;
                const int iB = iA + 8;
                pa[mi][0] = ps[iA * 132 + pc0 + kt * 8 + tig    ];
                pa[mi][1] = ps[iB * 132 + pc0 + kt * 8 + tig    ];
                pa[mi][2] = ps[iA * 132 + pc0 + kt * 8 + tig + 4];
                pa[mi][3] = ps[iB * 132 + pc0 + kt * 8 + tig + 4];
            }
#pragma unroll
            for (int nt = 0; nt < 8; ++nt) {
                const unsigned b0 = vs[(kt * 8 + tig    ) * 72 + nt * 8 + g];
                const unsigned b1 = vs[(kt * 8 + tig + 4) * 72 + nt * 8 + g];
                MMA(o[0][nt], pa[0], b0, b1);
                MMA(o[1][nt], pa[1], b0, b1);
            }
        }
    }

    // ---- epilogue: combine l, normalize, store g_ao as tf32 bits ----
#pragma unroll
    for (int mi = 0; mi < 2; ++mi)
#pragma unroll
        for (int hf = 0; hf < 2; ++hf) {
            float v = lsum[mi][hf];
            v += __shfl_xor_sync(0xffffffffu, v, 1);
            v += __shfl_xor_sync(0xffffffffu, v, 2);
            lsum[mi][hf] = v;
        }

    __syncthreads();
    float* lsm = (float*)ks;
    if (tig == 0) {
#pragma unroll
        for (int mi = 0; mi < 2; ++mi) {
            lsm[(rbase + mi * 16    ) * 2 + wn] = lsum[mi][0];
            lsm[(rbase + mi * 16 + 8) * 2 + wn] = lsum[mi][1];
        }
    }
    __syncthreads();

    const int bb = bh >> 3, hh = bh & 7;
#pragma unroll
    for (int mi = 0; mi < 2; ++mi) {
        const int iA = rbase + mi * 16;
        const int iB = iA + 8;
        const float ilA = 1.f / (lsm[iA * 2] + lsm[iA * 2 + 1]);
        const float ilB = 1.f / (lsm[iB * 2] + lsm[iB * 2 + 1]);
        float* baseA = g_ao + ((size_t)bb * NSEQ + (i0 + iA)) * DMODEL + hh * DIMH;
        float* baseB = g_ao + ((size_t)bb * NSEQ + (i0 + iB)) * DMODEL + hh * DIMH;
#pragma unroll
        for (int nt = 0; nt < 8; ++nt) {
            const int c = nt * 8 + 2 * tig;
            *(float2*)&baseA[c] = make_float2(
                __uint_as_float(f2tf(o[mi][nt][0] * ilA)),
                __uint_as_float(f2tf(o[mi][nt][1] * ilA)));
            *(float2*)&baseB[c] = make_float2(
                __uint_as_float(f2tf(o[mi][nt][2] * ilB)),
                __uint_as_float(f2tf(o[mi][nt][3] * ilB)));
        }
    }
}

// ============================================================================
// launcher
// ============================================================================
extern "C" void kernel_launch(void* const* d_in, const int* in_sizes, int n_in,
                              void* d_out, int out_size)
{
    const float* x         = (const float*)d_in[0];  // [32,512,512]
    const float* W_qkv     = (const float*)d_in[1];  // [512,1536]
    const float* rel_table = (const float*)d_in[2];  // [1025,64]
    const float* W_out     = (const float*)d_in[3];  // [512,512]
    const float* b_out     = (const float*)d_in[4];  // [512]
    float* out = (float*)d_out;                      // [32,512,512]

    float *xtf, *wqkv, *wout, *relq, *ao;
    cudaGetSymbolAddress((void**)&xtf,  g_xtf);
    cudaGetSymbolAddress((void**)&wqkv, g_wqkv);
    cudaGetSymbolAddress((void**)&wout, g_wout);
    cudaGetSymbolAddress((void**)&relq, g_rel);
    cudaGetSymbolAddress((void**)&ao,   g_ao);

    // 0. pre-convert fp32 -> tf32 bit patterns
    {
        int n4;
        n4 = MROWS * DMODEL / 4;
        cvt_kernel<<<(n4 + 255) / 256, 256>>>((const float4*)x, (float4*)xtf, n4);
        n4 = DMODEL * NQKV / 4;
        cvt_kernel<<<(n4 + 255) / 256, 256>>>((const float4*)W_qkv, (float4*)wqkv, n4);
        n4 = DMODEL * DMODEL / 4;
        cvt_kernel<<<(n4 + 255) / 256, 256>>>((const float4*)W_out, (float4*)wout, n4);
        n4 = 1025 * DIMH / 4;
        cvt_kernel<<<(n4 + 255) / 256, 256>>>((const float4*)rel_table, (float4*)relq, n4);
    }

    // 1. QKV projection
    cudaFuncSetAttribute(mm5_kernel<NQKV, true>,
                         cudaFuncAttributeMaxDynamicSharedMemorySize, MM5_SMEM_BYTES);
    mm5_kernel<NQKV, true><<<dim3(NQKV/128, MROWS/128), 128, MM5_SMEM_BYTES>>>(
        (const unsigned*)xtf, (const unsigned*)wqkv, nullptr, nullptr);

    // 2. fused attention
    cudaFuncSetAttribute(attn6_kernel,
                         cudaFuncAttributeMaxDynamicSharedMemorySize, ATT6_SMEM_BYTES);
    attn6_kernel<<<dim3(BH, NSEQ/64), 128, ATT6_SMEM_BYTES>>>();

    // 3. output projection
    cudaFuncSetAttribute(mm5_kernel<DMODEL, false>,
                         cudaFuncAttributeMaxDynamicSharedMemorySize, MM5_SMEM_BYTES);
    mm5_kernel<DMODEL, false><<<dim3(DMODEL/128, MROWS/128), 128, MM5_SMEM_BYTES>>>(
        (const unsigned*)ao, (const unsigned*)wout, b_out, out);
}

// round 13
// speedup vs baseline: 1.6082x; 1.5673x over previous
#include <cuda_runtime.h>
#include <cuda_fp16.h>

// Problem constants
#define HEADS   8
#define DIMH    64
#define NSEQ    512
#define BATCH   32
#define DMODEL  512
#define BH      (BATCH*HEADS)        // 256
#define NQKV    (3*HEADS*DIMH)       // 1536
#define MROWS   (BATCH*NSEQ)         // 16384
#define ATT_SCALE 0.125f             // 64^-0.5

// ---------------- scratch (device globals; no cudaMalloc allowed) -----------
// all fp16 bit patterns
__device__ __align__(16) unsigned short g_q    [BH*NSEQ*DIMH];
__device__ __align__(16) unsigned short g_k    [BH*NSEQ*DIMH];
__device__ __align__(16) unsigned short g_vT   [BH*DIMH*NSEQ];    // TRANSPOSED [bh][d][n]
__device__ __align__(16) unsigned short g_ao   [BATCH*NSEQ*DMODEL];
__device__ __align__(16) unsigned short g_xh   [MROWS*DMODEL];
__device__ __align__(16) unsigned short g_wqkvT[NQKV*DMODEL];     // [N][K]
__device__ __align__(16) unsigned short g_woutT[DMODEL*DMODEL];   // [N][K]
__device__ __align__(16) unsigned short g_relh [1025*DIMH];

// ---------------------------------------------------------------------------
// helpers
// ---------------------------------------------------------------------------
__device__ __forceinline__ unsigned f2h2(float lo, float hi) {
    unsigned r;
    asm("cvt.rn.f16x2.f32 %0, %1, %2;" : "=r"(r) : "f"(hi), "f"(lo));
    return r;
}
__device__ __forceinline__ unsigned short f2h(float x) {
    unsigned short r;
    asm("cvt.rn.f16.f32 %0, %1;" : "=h"(r) : "f"(x));
    return r;
}

// m16n8k16 fp16 mma, fp32 accumulate
__device__ __forceinline__ void mma_f16(float c[4], const unsigned a[4],
                                        unsigned b0, unsigned b1) {
    asm volatile(
        "mma.sync.aligned.m16n8k16.row.col.f32.f16.f16.f32 "
        "{%0,%1,%2,%3}, {%4,%5,%6,%7}, {%8,%9}, {%0,%1,%2,%3};\n"
        : "+f"(c[0]), "+f"(c[1]), "+f"(c[2]), "+f"(c[3])
        : "r"(a[0]), "r"(a[1]), "r"(a[2]), "r"(a[3]), "r"(b0), "r"(b1));
}
#define MMAH mma_f16

__device__ __forceinline__ void cp16(void* smem_dst, const void* gsrc) {
    unsigned s = (unsigned)__cvta_generic_to_shared(smem_dst);
    asm volatile("cp.async.cg.shared.global [%0], [%1], 16;\n" :: "r"(s), "l"(gsrc));
}
__device__ __forceinline__ void cp_commit() {
    asm volatile("cp.async.commit_group;\n");
}
template<int Nq>
__device__ __forceinline__ void cp_wait() {
    asm volatile("cp.async.wait_group %0;\n" :: "n"(Nq));
}
__device__ __forceinline__ void bar_pair(int id) {
    asm volatile("bar.sync %0, 64;" :: "r"(id) : "memory");
}

// ============================================================================
// cvt kernels: fp32 -> fp16
// ============================================================================
__global__ void __launch_bounds__(256) cvth_kernel(const float4* __restrict__ src,
                                                   uint2* __restrict__ dst, int n4)
{
    int i = blockIdx.x * 256 + threadIdx.x;
    if (i < n4) {
        float4 v = src[i];
        dst[i] = make_uint2(f2h2(v.x, v.y), f2h2(v.z, v.w));
    }
}

// cvt + transpose: dst[c][r] = fp16(src[r][c]);  src is [R x C] row-major.
__global__ void __launch_bounds__(256) cvtTh_kernel(const float* __restrict__ src,
                                                    unsigned short* __restrict__ dst,
                                                    int R, int C)
{
    __shared__ float t[32][33];
    const int tx = threadIdx.x, ty = threadIdx.y;   // block (32, 8)
    const int bx = blockIdx.x * 32, by = blockIdx.y * 32;
#pragma unroll
    for (int j = 0; j < 32; j += 8)
        t[ty + j][tx] = src[(size_t)(by + ty + j) * C + bx + tx];
    __syncthreads();
#pragma unroll
    for (int j = 0; j < 32; j += 8)
        dst[(size_t)(bx + ty + j) * R + by + tx] = f2h(t[tx][ty + j]);
}

// ============================================================================
// mm7: fp16 GEMM, C[M,N] = A[M,512] @ Bt[N,512]^T, fp32 accum.
// 128x128 CTA tile, 4 warps (2m x 2n), 64x64 warp tile, m16n8k16 mma.
// BK=32 (2 k16 chunks), 4-stage cp.async ring.
// smem/stage: As 128x20 w + Bs 128x20 w = 5120 w; x4 = 81920 B. 2 CTAs/SM.
// ============================================================================
#define MM7_STAGE_W (2 * 128 * 20)
#define MM7_SMEM_BYTES (4 * MM7_STAGE_W * 4)

template<int N, int SCAT>   // SCAT: 0=bias epilogue, 1=qkv scatter
__global__ void __launch_bounds__(128, 2) mm7_kernel(
    const unsigned short* __restrict__ A, const unsigned short* __restrict__ Bt,
    const float* __restrict__ bias, float* __restrict__ Cout)
{
    constexpr int K = 512;
    constexpr int ITERS = 16;      // K / 32
    extern __shared__ unsigned sm[];

    const int tid  = threadIdx.x;
    const int w    = tid >> 5, lane = tid & 31;
    const int g    = lane >> 2, tig = lane & 3;
    const int wm   = w >> 1, wn = w & 1;
    const int bm   = blockIdx.y * 128;
    const int bn   = blockIdx.x * 128;

    auto issue = [&](int it) {
        const int s  = it & 3;
        const int k0 = it * 32;                 // halves
        unsigned* As = sm + s * MM7_STAGE_W;
        unsigned* Bs = As + 128 * 20;
#pragma unroll
        for (int j = 0; j < 4; ++j) {
            const int c  = tid + j * 128;       // 0..511
            const int r  = c >> 2;              // row 0..127
            const int ch = c & 3;               // 16B chunk in row
            cp16(&As[r * 20 + ch * 4], A  + (size_t)(bm + r) * K + k0 + ch * 8);
            cp16(&Bs[r * 20 + ch * 4], Bt + (size_t)(bn + r) * K + k0 + ch * 8);
        }
    };

    float acc[4][8][4];
#pragma unroll
    for (int mi = 0; mi < 4; ++mi)
#pragma unroll
        for (int ni = 0; ni < 8; ++ni)
#pragma unroll
            for (int e = 0; e < 4; ++e) acc[mi][ni][e] = 0.f;

    issue(0); cp_commit();
    issue(1); cp_commit();
    issue(2); cp_commit();

    for (int it = 0; it < ITERS; ++it) {
        const int cur = it & 3;
        cp_wait<2>();
        __syncthreads();

        if (it + 3 < ITERS) issue(it + 3);
        cp_commit();

        const unsigned* As = sm + cur * MM7_STAGE_W;
        const unsigned* Bs = As + 128 * 20;
#pragma unroll
        for (int kt = 0; kt < 2; ++kt) {
            unsigned af[4][4];
#pragma unroll
            for (int mi = 0; mi < 4; ++mi) {
                const int base = wm * 64 + mi * 16;
                af[mi][0] = As[(base + g    ) * 20 + kt * 8 + tig    ];
                af[mi][1] = As[(base + g + 8) * 20 + kt * 8 + tig    ];
                af[mi][2] = As[(base + g    ) * 20 + kt * 8 + tig + 4];
                af[mi][3] = As[(base + g + 8) * 20 + kt * 8 + tig + 4];
            }
#pragma unroll
            for (int ni = 0; ni < 8; ++ni) {
                const int nr = wn * 64 + ni * 8 + g;
                const unsigned b0 = Bs[nr * 20 + kt * 8 + tig    ];
                const unsigned b1 = Bs[nr * 20 + kt * 8 + tig + 4];
#pragma unroll
                for (int mi = 0; mi < 4; ++mi)
                    MMAH(acc[mi][ni], af[mi], b0, b1);
            }
        }
    }

    // ---- epilogue ----
    if (SCAT) {
        const int which = bn >> 9;
        if (which < 2) {
            unsigned short* dst = (which == 0) ? g_q : g_k;
#pragma unroll
            for (int mi = 0; mi < 4; ++mi) {
                const int r0  = bm + wm * 64 + mi * 16 + g;
                const int bb  = r0 >> 9;
                const int nn0 = r0 & 511;
#pragma unroll
                for (int ni = 0; ni < 8; ++ni) {
                    const int c  = bn + wn * 64 + ni * 8 + 2 * tig;
                    const int h  = (c & 511) >> 6;
                    const int dd = c & 63;
                    const size_t rowbase = (size_t)((bb << 3) + h) * NSEQ;
                    *(unsigned*)&dst[((rowbase + nn0    )) * DIMH + dd] =
                        f2h2(acc[mi][ni][0], acc[mi][ni][1]);
                    *(unsigned*)&dst[((rowbase + nn0 + 8)) * DIMH + dd] =
                        f2h2(acc[mi][ni][2], acc[mi][ni][3]);
                }
            }
        } else {
            // V: transpose through smem, then coalesced writes to g_vT [bh][d][n]
            __syncthreads();
            unsigned short* tsm = (unsigned short*)sm;   // 128 x 136 halves
#pragma unroll
            for (int mi = 0; mi < 4; ++mi) {
                const int lr = wm * 64 + mi * 16 + g;
#pragma unroll
                for (int ni = 0; ni < 8; ++ni) {
                    const int lc = wn * 64 + ni * 8 + 2 * tig;
                    tsm[(lc    ) * 136 + lr    ] = f2h(acc[mi][ni][0]);
                    tsm[(lc + 1) * 136 + lr    ] = f2h(acc[mi][ni][1]);
                    tsm[(lc    ) * 136 + lr + 8] = f2h(acc[mi][ni][2]);
                    tsm[(lc + 1) * 136 + lr + 8] = f2h(acc[mi][ni][3]);
                }
            }
            __syncthreads();
            const int lc  = tid;                 // transposed row 0..127
            const int c   = bn + lc;
            const int h   = (c & 511) >> 6;
            const int dd  = c & 63;
            const int bb  = bm >> 9;
            const int nnb = bm & 511;
            unsigned short* dstp =
                g_vT + ((size_t)((bb << 3) + h) * DIMH + dd) * NSEQ + nnb;
#pragma unroll
            for (int u = 0; u < 16; ++u)
                *(uint4*)(dstp + u * 8) = *(const uint4*)(tsm + lc * 136 + u * 8);
        }
    } else {
#pragma unroll
        for (int mi = 0; mi < 4; ++mi) {
            const int r = bm + wm * 64 + mi * 16 + g;
#pragma unroll
            for (int ni = 0; ni < 8; ++ni) {
                const int c = bn + wn * 64 + ni * 8 + 2 * tig;
                const float2 bv = *(const float2*)&bias[c];
                *(float2*)&Cout[(size_t)r * N + c] =
                    make_float2(acc[mi][ni][0] + bv.x, acc[mi][ni][1] + bv.y);
                *(float2*)&Cout[(size_t)(r + 8) * N + c] =
                    make_float2(acc[mi][ni][2] + bv.x, acc[mi][ni][3] + bv.y);
            }
        }
    }
}

// ============================================================================
// attn7: fp16-mma flash attention (m16n8k16), 2x2 warp layout, max-free
// softmax, incremental PB chunks, cp.async prefetch after S3, pair barriers.
// V consumed from g_vT ([bh][d][n], k-contiguous for the PV B operand).
// smem (words): rels 64x36 | ks 64x36 (l-exchange alias) | vs 2x64x36 |
//               pbs 64x132 floats.  Total 17664 w = 70,656 B. 2 CTAs/SM.
// ============================================================================
#define ATT7_SMEM_WORDS (2304 + 2304 + 4608 + 8448)
#define ATT7_SMEM_BYTES (ATT7_SMEM_WORDS * 4)

__global__ void __launch_bounds__(128, 2) attn7_kernel()
{
    extern __shared__ unsigned smu[];
    unsigned* rels  = smu;                    // 64 x 36 (Q staging alias)
    unsigned* ks    = smu + 2304;             // 64 x 36 (l-exchange alias)
    unsigned* vsbuf = smu + 4608;             // 2 x 64 x 36
    float*    pbs   = (float*)(smu + 9216);   // 64 x 132
    unsigned* ps    = (unsigned*)pbs;

    const int tid  = threadIdx.x;
    const int w    = tid >> 5;
    const int lane = tid & 31;
    const int g    = lane >> 2;
    const int tig  = lane & 3;
    const int wm   = w >> 1, wn = w & 1;

    const int bh = blockIdx.x;
    const int qb = blockIdx.y;
    const int i0 = qb * 64;
    const int rbase = wm * 32 + g;
    const int pbar  = wm + 1;

    const unsigned short* qg = g_q  + ((size_t)bh * NSEQ + i0) * DIMH;
    const unsigned short* kg = g_k  + (size_t)bh * NSEQ * DIMH;
    const unsigned short* vg = g_vT + (size_t)bh * DIMH * NSEQ;
    const unsigned short* rg = g_relh;

    // 64 rows x 64 halves tile -> smem rows of 36 words; srcstride in halves
    auto copy_tile = [&](unsigned* dst, const unsigned short* src, int srcstride) {
#pragma unroll
        for (int k = 0; k < 4; ++k) {
            const int c  = tid + k * 128;      // chunk 0..511
            const int r  = c >> 3;             // row 0..63
            const int ch = c & 7;              // 16B chunk (8 halves)
            cp16(&dst[r * 36 + ch * 4], src + (size_t)r * srcstride + ch * 8);
        }
    };

    auto issue_tiles = [&](int t) {
        const int j0 = t * 64;
        copy_tile(ks, kg + (size_t)j0 * DIMH, 64);
        copy_tile(vsbuf + (t & 1) * 2304, vg + j0, NSEQ);   // rows d, stride 512
        copy_tile(rels, rg + (size_t)(i0 + 449 - j0) * DIMH, 64);
    };

    // ---- stage Q ----
    copy_tile(rels, qg, 64);
    cp_commit();
    cp_wait<0>();
    __syncthreads();

    // ---- Q A-fragments (4 k16 chunks) ----
    unsigned qa[2][4][4];
#pragma unroll
    for (int mi = 0; mi < 2; ++mi) {
        const int r0 = rbase + mi * 16;
#pragma unroll
        for (int kt = 0; kt < 4; ++kt) {
            qa[mi][kt][0] = rels[ r0      * 36 + kt * 8 + tig    ];
            qa[mi][kt][1] = rels[(r0 + 8) * 36 + kt * 8 + tig    ];
            qa[mi][kt][2] = rels[ r0      * 36 + kt * 8 + tig + 4];
            qa[mi][kt][3] = rels[(r0 + 8) * 36 + kt * 8 + tig + 4];
        }
    }
    __syncthreads();   // rels free

    // ---- prologue: rel chunk(-1) -> pbs half 1 ----
    {
        copy_tile(rels, rg + (size_t)(i0 + 513) * DIMH, 64);
        cp_commit();
        cp_wait<0>();
        __syncthreads();
#pragma unroll
        for (int nt = 0; nt < 4; ++nt) {
            float a0[4] = {0.f,0.f,0.f,0.f}, a1[4] = {0.f,0.f,0.f,0.f};
            const int dr = wn * 32 + nt * 8 + g;
#pragma unroll
            for (int kt = 0; kt < 4; ++kt) {
                const unsigned b0 = rels[dr * 36 + kt * 8 + tig    ];
                const unsigned b1 = rels[dr * 36 + kt * 8 + tig + 4];
                MMAH(a0, qa[0][kt], b0, b1);
                MMAH(a1, qa[1][kt], b0, b1);
            }
            const int col = 64 + wn * 32 + nt * 8 + 2 * tig;
            *(float2*)&pbs[(rbase     ) * 132 + col] = make_float2(a0[0], a0[1]);
            *(float2*)&pbs[(rbase +  8) * 132 + col] = make_float2(a0[2], a0[3]);
            *(float2*)&pbs[(rbase + 16) * 132 + col] = make_float2(a1[0], a1[1]);
            *(float2*)&pbs[(rbase + 24) * 132 + col] = make_float2(a1[2], a1[3]);
        }
    }
    __syncthreads();

    issue_tiles(0);
    cp_commit();

    float lsum[2][2] = {{0.f, 0.f}, {0.f, 0.f}};
    float o[2][8][4];
#pragma unroll
    for (int mi = 0; mi < 2; ++mi)
#pragma unroll
        for (int nt = 0; nt < 8; ++nt)
#pragma unroll
            for (int e = 0; e < 4; ++e) o[mi][nt][e] = 0.f;

    for (int t = 0; t < 8; ++t) {
        const int h = t & 1;
        const unsigned* vs = vsbuf + h * 2304;

        cp_wait<0>();
        __syncthreads();               // S2: tiles t ready; all past PV(t-1)

        // ---- PB new chunk -> pbs half h ----
#pragma unroll
        for (int nt = 0; nt < 4; ++nt) {
            float a0[4] = {0.f,0.f,0.f,0.f}, a1[4] = {0.f,0.f,0.f,0.f};
            const int dr = wn * 32 + nt * 8 + g;
#pragma unroll
            for (int kt = 0; kt < 4; ++kt) {
                const unsigned b0 = rels[dr * 36 + kt * 8 + tig    ];
                const unsigned b1 = rels[dr * 36 + kt * 8 + tig + 4];
                MMAH(a0, qa[0][kt], b0, b1);
                MMAH(a1, qa[1][kt], b0, b1);
            }
            const int col = h * 64 + wn * 32 + nt * 8 + 2 * tig;
            *(float2*)&pbs[(rbase     ) * 132 + col] = make_float2(a0[0], a0[1]);
            *(float2*)&pbs[(rbase +  8) * 132 + col] = make_float2(a0[2], a0[3]);
            *(float2*)&pbs[(rbase + 16) * 132 + col] = make_float2(a1[0], a1[1]);
            *(float2*)&pbs[(rbase + 24) * 132 + col] = make_float2(a1[2], a1[3]);
        }

        // ---- QK ----
        float s[2][4][4];
#pragma unroll
        for (int nt = 0; nt < 4; ++nt) {
            const int jr = wn * 32 + nt * 8 + g;
#pragma unroll
            for (int mi = 0; mi < 2; ++mi)
                s[mi][nt][0] = s[mi][nt][1] = s[mi][nt][2] = s[mi][nt][3] = 0.f;
#pragma unroll
            for (int kt = 0; kt < 4; ++kt) {
                const unsigned b0 = ks[jr * 36 + kt * 8 + tig    ];
                const unsigned b1 = ks[jr * 36 + kt * 8 + tig + 4];
                MMAH(s[0][nt], qa[0][kt], b0, b1);
                MMAH(s[1][nt], qa[1][kt], b0, b1);
            }
        }
        __syncthreads();               // S3 (CTA): pbs visible; ks/rels free

        if (t + 1 < 8) issue_tiles(t + 1);
        cp_commit();

        // ---- bias gather + exp + partial sums ----
#pragma unroll
        for (int mi = 0; mi < 2; ++mi) {
            const int iA = rbase + mi * 16;
            const int iB = iA + 8;
#pragma unroll
            for (int nt = 0; nt < 4; ++nt) {
                const int jj = wn * 32 + nt * 8 + 2 * tig;
                const int oA0 = iA - jj + 63, oA1 = oA0 - 1;
                const int oB0 = iB - jj + 63, oB1 = oB0 - 1;
                const int pA0 = ((h ^ (oA0 >> 6)) << 6) | (oA0 & 63);
                const int pA1 = ((h ^ (oA1 >> 6)) << 6) | (oA1 & 63);
                const int pB0 = ((h ^ (oB0 >> 6)) << 6) | (oB0 & 63);
                const int pB1 = ((h ^ (oB1 >> 6)) << 6) | (oB1 & 63);
                float e0 = __expf((s[mi][nt][0] + pbs[iA * 132 + pA0]) * ATT_SCALE);
                float e1 = __expf((s[mi][nt][1] + pbs[iA * 132 + pA1]) * ATT_SCALE);
                float e2 = __expf((s[mi][nt][2] + pbs[iB * 132 + pB0]) * ATT_SCALE);
                float e3 = __expf((s[mi][nt][3] + pbs[iB * 132 + pB1]) * ATT_SCALE);
                s[mi][nt][0] = e0; s[mi][nt][1] = e1;
                s[mi][nt][2] = e2; s[mi][nt][3] = e3;
                lsum[mi][0] += e0 + e1;
                lsum[mi][1] += e2 + e3;
            }
        }
        bar_pair(pbar);                // S4 (pair)

        // ---- write P (fp16x2) into dead half (h^1): 32 words per row ----
        const int pc0 = (h ^ 1) * 64;
#pragma unroll
        for (int mi = 0; mi < 2; ++mi) {
            const int iA = rbase + mi * 16;
            const int iB = iA + 8;
#pragma unroll
            for (int nt = 0; nt < 4; ++nt) {
                const int widx = pc0 + wn * 16 + nt * 4 + tig;
                ps[iA * 132 + widx] = f2h2(s[mi][nt][0], s[mi][nt][1]);
                ps[iB * 132 + widx] = f2h2(s[mi][nt][2], s[mi][nt][3]);
            }
        }
        bar_pair(pbar);                // S5 (pair)

        // ---- O += P @ V  (V from transposed tile: rows d) ----
#pragma unroll
        for (int kt = 0; kt < 4; ++kt) {
            unsigned pa[2][4];
#pragma unroll
            for (int mi = 0; mi < 2; ++mi) {
                const int iA = rbase + mi * 16;
                const int iB = iA + 8;
                pa[mi][0] = ps[iA * 132 + pc0 + kt * 8 + tig    ];
                pa[mi][1] = ps[iB * 132 + pc0 + kt * 8 + tig    ];
                pa[mi][2] = ps[iA * 132 + pc0 + kt * 8 + tig + 4];
                pa[mi][3] = ps[iB * 132 + pc0 + kt * 8 + tig + 4];
            }
#pragma unroll
            for (int nt = 0; nt < 8; ++nt) {
                const int dr = nt * 8 + g;     // d row of vT tile
                const unsigned b0 = vs[dr * 36 + kt * 8 + tig    ];
                const unsigned b1 = vs[dr * 36 + kt * 8 + tig + 4];
                MMAH(o[0][nt], pa[0], b0, b1);
                MMAH(o[1][nt], pa[1], b0, b1);
            }
        }
    }

    // ---- epilogue: combine l, normalize, store g_ao fp16 ----
#pragma unroll
    for (int mi = 0; mi < 2; ++mi)
#pragma unroll
        for (int hf = 0; hf < 2; ++hf) {
            float v = lsum[mi][hf];
            v += __shfl_xor_sync(0xffffffffu, v, 1);
            v += __shfl_xor_sync(0xffffffffu, v, 2);
            lsum[mi][hf] = v;
        }

    __syncthreads();
    float* lsm = (float*)ks;
    if (tig == 0) {
#pragma unroll
        for (int mi = 0; mi < 2; ++mi) {
            lsm[(rbase + mi * 16    ) * 2 + wn] = lsum[mi][0];
            lsm[(rbase + mi * 16 + 8) * 2 + wn] = lsum[mi][1];
        }
    }
    __syncthreads();

    const int bb = bh >> 3, hh = bh & 7;
#pragma unroll
    for (int mi = 0; mi < 2; ++mi) {
        const int iA = rbase + mi * 16;
        const int iB = iA + 8;
        const float ilA = 1.f / (lsm[iA * 2] + lsm[iA * 2 + 1]);
        const float ilB = 1.f / (lsm[iB * 2] + lsm[iB * 2 + 1]);
        unsigned short* baseA = g_ao + ((size_t)bb * NSEQ + (i0 + iA)) * DMODEL + hh * DIMH;
        unsigned short* baseB = g_ao + ((size_t)bb * NSEQ + (i0 + iB)) * DMODEL + hh * DIMH;
#pragma unroll
        for (int nt = 0; nt < 8; ++nt) {
            const int c = nt * 8 + 2 * tig;
            *(unsigned*)&baseA[c] = f2h2(o[mi][nt][0] * ilA, o[mi][nt][1] * ilA);
            *(unsigned*)&baseB[c] = f2h2(o[mi][nt][2] * ilB, o[mi][nt][3] * ilB);
        }
    }
}

// ============================================================================
// launcher
// ============================================================================
extern "C" void kernel_launch(void* const* d_in, const int* in_sizes, int n_in,
                              void* d_out, int out_size)
{
    const float* x         = (const float*)d_in[0];  // [32,512,512]
    const float* W_qkv     = (const float*)d_in[1];  // [512,1536]
    const float* rel_table = (const float*)d_in[2];  // [1025,64]
    const float* W_out     = (const float*)d_in[3];  // [512,512]
    const float* b_out     = (const float*)d_in[4];  // [512]
    float* out = (float*)d_out;                      // [32,512,512]

    unsigned short *xh, *wqkvT, *woutT, *relh, *ao;
    cudaGetSymbolAddress((void**)&xh,    g_xh);
    cudaGetSymbolAddress((void**)&wqkvT, g_wqkvT);
    cudaGetSymbolAddress((void**)&woutT, g_woutT);
    cudaGetSymbolAddress((void**)&relh,  g_relh);
    cudaGetSymbolAddress((void**)&ao,    g_ao);

    // 0. pre-convert fp32 -> fp16 (weights transposed to [N][K])
    {
        int n4 = MROWS * DMODEL / 4;
        cvth_kernel<<<(n4 + 255) / 256, 256>>>((const float4*)x, (uint2*)xh, n4);
        n4 = 1025 * DIMH / 4;
        cvth_kernel<<<(n4 + 255) / 256, 256>>>((const float4*)rel_table, (uint2*)relh, n4);
        cvtTh_kernel<<<dim3(NQKV / 32, DMODEL / 32), dim3(32, 8)>>>(W_qkv, wqkvT, DMODEL, NQKV);
        cvtTh_kernel<<<dim3(DMODEL / 32, DMODEL / 32), dim3(32, 8)>>>(W_out, woutT, DMODEL, DMODEL);
    }

    // 1. QKV projection (fp16 mma, fused scatter; V transposed)
    cudaFuncSetAttribute(mm7_kernel<NQKV, 1>,
                         cudaFuncAttributeMaxDynamicSharedMemorySize, MM7_SMEM_BYTES);
    mm7_kernel<NQKV, 1><<<dim3(NQKV / 128, MROWS / 128), 128, MM7_SMEM_BYTES>>>(
        xh, wqkvT, nullptr, nullptr);

    // 2. fused fp16-mma attention
    cudaFuncSetAttribute(attn7_kernel,
                         cudaFuncAttributeMaxDynamicSharedMemorySize, ATT7_SMEM_BYTES);
    attn7_kernel<<<dim3(BH, NSEQ / 64), 128, ATT7_SMEM_BYTES>>>();

    // 3. output projection (fp16 mma, fused bias)
    cudaFuncSetAttribute(mm7_kernel<DMODEL, 0>,
                         cudaFuncAttributeMaxDynamicSharedMemorySize, MM7_SMEM_BYTES);
    mm7_kernel<DMODEL, 0><<<dim3(DMODEL / 128, MROWS / 128), 128, MM7_SMEM_BYTES>>>(
        ao, woutT, b_out, out);
}

// round 14
// speedup vs baseline: 1.7014x; 1.0579x over previous
#include <cuda_runtime.h>
#include <cuda_fp16.h>

// Problem constants
#define HEADS   8
#define DIMH    64
#define NSEQ    512
#define BATCH   32
#define DMODEL  512
#define BH      (BATCH*HEADS)        // 256
#define NQKV    (3*HEADS*DIMH)       // 1536
#define MROWS   (BATCH*NSEQ)         // 16384
#define ATT_SCALE 0.125f             // 64^-0.5

// ---------------- scratch (device globals; no cudaMalloc allowed) -----------
// all fp16 bit patterns
__device__ __align__(16) unsigned short g_q    [BH*NSEQ*DIMH];
__device__ __align__(16) unsigned short g_k    [BH*NSEQ*DIMH];
__device__ __align__(16) unsigned short g_vT   [BH*DIMH*NSEQ];    // TRANSPOSED [bh][d][n]
__device__ __align__(16) unsigned short g_ao   [BATCH*NSEQ*DMODEL];
__device__ __align__(16) unsigned short g_xh   [MROWS*DMODEL];
__device__ __align__(16) unsigned short g_wqkvT[NQKV*DMODEL];     // [N][K]
__device__ __align__(16) unsigned short g_woutT[DMODEL*DMODEL];   // [N][K]
__device__ __align__(16) unsigned short g_relh [1025*DIMH];

// ---------------------------------------------------------------------------
// helpers
// ---------------------------------------------------------------------------
__device__ __forceinline__ unsigned f2h2(float lo, float hi) {
    unsigned r;
    asm("cvt.rn.f16x2.f32 %0, %1, %2;" : "=r"(r) : "f"(hi), "f"(lo));
    return r;
}
__device__ __forceinline__ unsigned short f2h(float x) {
    unsigned short r;
    asm("cvt.rn.f16.f32 %0, %1;" : "=h"(r) : "f"(x));
    return r;
}

// m16n8k16 fp16 mma, fp32 accumulate
__device__ __forceinline__ void mma_f16(float c[4], const unsigned a[4],
                                        unsigned b0, unsigned b1) {
    asm volatile(
        "mma.sync.aligned.m16n8k16.row.col.f32.f16.f16.f32 "
        "{%0,%1,%2,%3}, {%4,%5,%6,%7}, {%8,%9}, {%0,%1,%2,%3};\n"
        : "+f"(c[0]), "+f"(c[1]), "+f"(c[2]), "+f"(c[3])
        : "r"(a[0]), "r"(a[1]), "r"(a[2]), "r"(a[3]), "r"(b0), "r"(b1));
}
#define MMAH mma_f16

__device__ __forceinline__ void cp16(void* smem_dst, const void* gsrc) {
    unsigned s = (unsigned)__cvta_generic_to_shared(smem_dst);
    asm volatile("cp.async.cg.shared.global [%0], [%1], 16;\n" :: "r"(s), "l"(gsrc));
}
__device__ __forceinline__ void cp_commit() {
    asm volatile("cp.async.commit_group;\n");
}
template<int Nq>
__device__ __forceinline__ void cp_wait() {
    asm volatile("cp.async.wait_group %0;\n" :: "n"(Nq));
}
__device__ __forceinline__ void bar_pair(int id) {
    asm volatile("bar.sync %0, 64;" :: "r"(id) : "memory");
}

// ============================================================================
// cvt kernels: fp32 -> fp16
// ============================================================================
__global__ void __launch_bounds__(256) cvth_kernel(const float4* __restrict__ src,
                                                   uint2* __restrict__ dst, int n4)
{
    int i = blockIdx.x * 256 + threadIdx.x;
    if (i < n4) {
        float4 v = src[i];
        dst[i] = make_uint2(f2h2(v.x, v.y), f2h2(v.z, v.w));
    }
}

// cvt + transpose: dst[c][r] = fp16(src[r][c]);  src is [R x C] row-major.
__global__ void __launch_bounds__(256) cvtTh_kernel(const float* __restrict__ src,
                                                    unsigned short* __restrict__ dst,
                                                    int R, int C)
{
    __shared__ float t[32][33];
    const int tx = threadIdx.x, ty = threadIdx.y;   // block (32, 8)
    const int bx = blockIdx.x * 32, by = blockIdx.y * 32;
#pragma unroll
    for (int j = 0; j < 32; j += 8)
        t[ty + j][tx] = src[(size_t)(by + ty + j) * C + bx + tx];
    __syncthreads();
#pragma unroll
    for (int j = 0; j < 32; j += 8)
        dst[(size_t)(bx + ty + j) * R + by + tx] = f2h(t[tx][ty + j]);
}

// ============================================================================
// mm7: fp16 GEMM, C[M,N] = A[M,512] @ Bt[N,512]^T, fp32 accum.
// 128x128 CTA tile, 4 warps (2m x 2n), 64x64 warp tile, m16n8k16 mma.
// BK=32 (2 k16 chunks), 4-stage cp.async ring. (unchanged from R13)
// ============================================================================
#define MM7_STAGE_W (2 * 128 * 20)
#define MM7_SMEM_BYTES (4 * MM7_STAGE_W * 4)

template<int N, int SCAT>   // SCAT: 0=bias epilogue, 1=qkv scatter
__global__ void __launch_bounds__(128, 2) mm7_kernel(
    const unsigned short* __restrict__ A, const unsigned short* __restrict__ Bt,
    const float* __restrict__ bias, float* __restrict__ Cout)
{
    constexpr int K = 512;
    constexpr int ITERS = 16;      // K / 32
    extern __shared__ unsigned sm[];

    const int tid  = threadIdx.x;
    const int w    = tid >> 5, lane = tid & 31;
    const int g    = lane >> 2, tig = lane & 3;
    const int wm   = w >> 1, wn = w & 1;
    const int bm   = blockIdx.y * 128;
    const int bn   = blockIdx.x * 128;

    auto issue = [&](int it) {
        const int s  = it & 3;
        const int k0 = it * 32;                 // halves
        unsigned* As = sm + s * MM7_STAGE_W;
        unsigned* Bs = As + 128 * 20;
#pragma unroll
        for (int j = 0; j < 4; ++j) {
            const int c  = tid + j * 128;       // 0..511
            const int r  = c >> 2;              // row 0..127
            const int ch = c & 3;               // 16B chunk in row
            cp16(&As[r * 20 + ch * 4], A  + (size_t)(bm + r) * K + k0 + ch * 8);
            cp16(&Bs[r * 20 + ch * 4], Bt + (size_t)(bn + r) * K + k0 + ch * 8);
        }
    };

    float acc[4][8][4];
#pragma unroll
    for (int mi = 0; mi < 4; ++mi)
#pragma unroll
        for (int ni = 0; ni < 8; ++ni)
#pragma unroll
            for (int e = 0; e < 4; ++e) acc[mi][ni][e] = 0.f;

    issue(0); cp_commit();
    issue(1); cp_commit();
    issue(2); cp_commit();

    for (int it = 0; it < ITERS; ++it) {
        const int cur = it & 3;
        cp_wait<2>();
        __syncthreads();

        if (it + 3 < ITERS) issue(it + 3);
        cp_commit();

        const unsigned* As = sm + cur * MM7_STAGE_W;
        const unsigned* Bs = As + 128 * 20;
#pragma unroll
        for (int kt = 0; kt < 2; ++kt) {
            unsigned af[4][4];
#pragma unroll
            for (int mi = 0; mi < 4; ++mi) {
                const int base = wm * 64 + mi * 16;
                af[mi][0] = As[(base + g    ) * 20 + kt * 8 + tig    ];
                af[mi][1] = As[(base + g + 8) * 20 + kt * 8 + tig    ];
                af[mi][2] = As[(base + g    ) * 20 + kt * 8 + tig + 4];
                af[mi][3] = As[(base + g + 8) * 20 + kt * 8 + tig + 4];
            }
#pragma unroll
            for (int ni = 0; ni < 8; ++ni) {
                const int nr = wn * 64 + ni * 8 + g;
                const unsigned b0 = Bs[nr * 20 + kt * 8 + tig    ];
                const unsigned b1 = Bs[nr * 20 + kt * 8 + tig + 4];
#pragma unroll
                for (int mi = 0; mi < 4; ++mi)
                    MMAH(acc[mi][ni], af[mi], b0, b1);
            }
        }
    }

    // ---- epilogue ----
    if (SCAT) {
        const int which = bn >> 9;
        if (which < 2) {
            unsigned short* dst = (which == 0) ? g_q : g_k;
#pragma unroll
            for (int mi = 0; mi < 4; ++mi) {
                const int r0  = bm + wm * 64 + mi * 16 + g;
                const int bb  = r0 >> 9;
                const int nn0 = r0 & 511;
#pragma unroll
                for (int ni = 0; ni < 8; ++ni) {
                    const int c  = bn + wn * 64 + ni * 8 + 2 * tig;
                    const int h  = (c & 511) >> 6;
                    const int dd = c & 63;
                    const size_t rowbase = (size_t)((bb << 3) + h) * NSEQ;
                    *(unsigned*)&dst[((rowbase + nn0    )) * DIMH + dd] =
                        f2h2(acc[mi][ni][0], acc[mi][ni][1]);
                    *(unsigned*)&dst[((rowbase + nn0 + 8)) * DIMH + dd] =
                        f2h2(acc[mi][ni][2], acc[mi][ni][3]);
                }
            }
        } else {
            // V: transpose through smem, then coalesced writes to g_vT [bh][d][n]
            __syncthreads();
            unsigned short* tsm = (unsigned short*)sm;   // 128 x 136 halves
#pragma unroll
            for (int mi = 0; mi < 4; ++mi) {
                const int lr = wm * 64 + mi * 16 + g;
#pragma unroll
                for (int ni = 0; ni < 8; ++ni) {
                    const int lc = wn * 64 + ni * 8 + 2 * tig;
                    tsm[(lc    ) * 136 + lr    ] = f2h(acc[mi][ni][0]);
                    tsm[(lc + 1) * 136 + lr    ] = f2h(acc[mi][ni][1]);
                    tsm[(lc    ) * 136 + lr + 8] = f2h(acc[mi][ni][2]);
                    tsm[(lc + 1) * 136 + lr + 8] = f2h(acc[mi][ni][3]);
                }
            }
            __syncthreads();
            const int lc  = tid;                 // transposed row 0..127
            const int c   = bn + lc;
            const int h   = (c & 511) >> 6;
            const int dd  = c & 63;
            const int bb  = bm >> 9;
            const int nnb = bm & 511;
            unsigned short* dstp =
                g_vT + ((size_t)((bb << 3) + h) * DIMH + dd) * NSEQ + nnb;
#pragma unroll
            for (int u = 0; u < 16; ++u)
                *(uint4*)(dstp + u * 8) = *(const uint4*)(tsm + lc * 136 + u * 8);
        }
    } else {
#pragma unroll
        for (int mi = 0; mi < 4; ++mi) {
            const int r = bm + wm * 64 + mi * 16 + g;
#pragma unroll
            for (int ni = 0; ni < 8; ++ni) {
                const int c = bn + wn * 64 + ni * 8 + 2 * tig;
                const float2 bv = *(const float2*)&bias[c];
                *(float2*)&Cout[(size_t)r * N + c] =
                    make_float2(acc[mi][ni][0] + bv.x, acc[mi][ni][1] + bv.y);
                *(float2*)&Cout[(size_t)(r + 8) * N + c] =
                    make_float2(acc[mi][ni][2] + bv.x, acc[mi][ni][3] + bv.y);
            }
        }
    }
}

// ============================================================================
// attn7 (R13) with occupancy bump: smem 70,656 B/CTA -> 3 CTAs/SM.
// __launch_bounds__(128, 3): 12 warps/SM resident, 4.6 waves (was 6.9).
// ============================================================================
#define ATT7_SMEM_WORDS (2304 + 2304 + 4608 + 8448)
#define ATT7_SMEM_BYTES (ATT7_SMEM_WORDS * 4)

__global__ void __launch_bounds__(128, 3) attn7_kernel()
{
    extern __shared__ unsigned smu[];
    unsigned* rels  = smu;                    // 64 x 36 (Q staging alias)
    unsigned* ks    = smu + 2304;             // 64 x 36 (l-exchange alias)
    unsigned* vsbuf = smu + 4608;             // 2 x 64 x 36
    float*    pbs   = (float*)(smu + 9216);   // 64 x 132
    unsigned* ps    = (unsigned*)pbs;

    const int tid  = threadIdx.x;
    const int w    = tid >> 5;
    const int lane = tid & 31;
    const int g    = lane >> 2;
    const int tig  = lane & 3;
    const int wm   = w >> 1, wn = w & 1;

    const int bh = blockIdx.x;
    const int qb = blockIdx.y;
    const int i0 = qb * 64;
    const int rbase = wm * 32 + g;
    const int pbar  = wm + 1;

    const unsigned short* qg = g_q  + ((size_t)bh * NSEQ + i0) * DIMH;
    const unsigned short* kg = g_k  + (size_t)bh * NSEQ * DIMH;
    const unsigned short* vg = g_vT + (size_t)bh * DIMH * NSEQ;
    const unsigned short* rg = g_relh;

    auto copy_tile = [&](unsigned* dst, const unsigned short* src, int srcstride) {
#pragma unroll
        for (int k = 0; k < 4; ++k) {
            const int c  = tid + k * 128;      // chunk 0..511
            const int r  = c >> 3;             // row 0..63
            const int ch = c & 7;              // 16B chunk (8 halves)
            cp16(&dst[r * 36 + ch * 4], src + (size_t)r * srcstride + ch * 8);
        }
    };

    auto issue_tiles = [&](int t) {
        const int j0 = t * 64;
        copy_tile(ks, kg + (size_t)j0 * DIMH, 64);
        copy_tile(vsbuf + (t & 1) * 2304, vg + j0, NSEQ);   // rows d, stride 512
        copy_tile(rels, rg + (size_t)(i0 + 449 - j0) * DIMH, 64);
    };

    // ---- stage Q ----
    copy_tile(rels, qg, 64);
    cp_commit();
    cp_wait<0>();
    __syncthreads();

    // ---- Q A-fragments (4 k16 chunks) ----
    unsigned qa[2][4][4];
#pragma unroll
    for (int mi = 0; mi < 2; ++mi) {
        const int r0 = rbase + mi * 16;
#pragma unroll
        for (int kt = 0; kt < 4; ++kt) {
            qa[mi][kt][0] = rels[ r0      * 36 + kt * 8 + tig    ];
            qa[mi][kt][1] = rels[(r0 + 8) * 36 + kt * 8 + tig    ];
            qa[mi][kt][2] = rels[ r0      * 36 + kt * 8 + tig + 4];
            qa[mi][kt][3] = rels[(r0 + 8) * 36 + kt * 8 + tig + 4];
        }
    }
    __syncthreads();   // rels free

    // ---- prologue: rel chunk(-1) -> pbs half 1 ----
    {
        copy_tile(rels, rg + (size_t)(i0 + 513) * DIMH, 64);
        cp_commit();
        cp_wait<0>();
        __syncthreads();
#pragma unroll
        for (int nt = 0; nt < 4; ++nt) {
            float a0[4] = {0.f,0.f,0.f,0.f}, a1[4] = {0.f,0.f,0.f,0.f};
            const int dr = wn * 32 + nt * 8 + g;
#pragma unroll
            for (int kt = 0; kt < 4; ++kt) {
                const unsigned b0 = rels[dr * 36 + kt * 8 + tig    ];
                const unsigned b1 = rels[dr * 36 + kt * 8 + tig + 4];
                MMAH(a0, qa[0][kt], b0, b1);
                MMAH(a1, qa[1][kt], b0, b1);
            }
            const int col = 64 + wn * 32 + nt * 8 + 2 * tig;
            *(float2*)&pbs[(rbase     ) * 132 + col] = make_float2(a0[0], a0[1]);
            *(float2*)&pbs[(rbase +  8) * 132 + col] = make_float2(a0[2], a0[3]);
            *(float2*)&pbs[(rbase + 16) * 132 + col] = make_float2(a1[0], a1[1]);
            *(float2*)&pbs[(rbase + 24) * 132 + col] = make_float2(a1[2], a1[3]);
        }
    }
    __syncthreads();

    issue_tiles(0);
    cp_commit();

    float lsum[2][2] = {{0.f, 0.f}, {0.f, 0.f}};
    float o[2][8][4];
#pragma unroll
    for (int mi = 0; mi < 2; ++mi)
#pragma unroll
        for (int nt = 0; nt < 8; ++nt)
#pragma unroll
            for (int e = 0; e < 4; ++e) o[mi][nt][e] = 0.f;

    for (int t = 0; t < 8; ++t) {
        const int h = t & 1;
        const unsigned* vs = vsbuf + h * 2304;

        cp_wait<0>();
        __syncthreads();               // S2: tiles t ready; all past PV(t-1)

        // ---- PB new chunk -> pbs half h ----
#pragma unroll
        for (int nt = 0; nt < 4; ++nt) {
            float a0[4] = {0.f,0.f,0.f,0.f}, a1[4] = {0.f,0.f,0.f,0.f};
            const int dr = wn * 32 + nt * 8 + g;
#pragma unroll
            for (int kt = 0; kt < 4; ++kt) {
                const unsigned b0 = rels[dr * 36 + kt * 8 + tig    ];
                const unsigned b1 = rels[dr * 36 + kt * 8 + tig + 4];
                MMAH(a0, qa[0][kt], b0, b1);
                MMAH(a1, qa[1][kt], b0, b1);
            }
            const int col = h * 64 + wn * 32 + nt * 8 + 2 * tig;
            *(float2*)&pbs[(rbase     ) * 132 + col] = make_float2(a0[0], a0[1]);
            *(float2*)&pbs[(rbase +  8) * 132 + col] = make_float2(a0[2], a0[3]);
            *(float2*)&pbs[(rbase + 16) * 132 + col] = make_float2(a1[0], a1[1]);
            *(float2*)&pbs[(rbase + 24) * 132 + col] = make_float2(a1[2], a1[3]);
        }

        // ---- QK ----
        float s[2][4][4];
#pragma unroll
        for (int nt = 0; nt < 4; ++nt) {
            const int jr = wn * 32 + nt * 8 + g;
#pragma unroll
            for (int mi = 0; mi < 2; ++mi)
                s[mi][nt][0] = s[mi][nt][1] = s[mi][nt][2] = s[mi][nt][3] = 0.f;
#pragma unroll
            for (int kt = 0; kt < 4; ++kt) {
                const unsigned b0 = ks[jr * 36 + kt * 8 + tig    ];
                const unsigned b1 = ks[jr * 36 + kt * 8 + tig + 4];
                MMAH(s[0][nt], qa[0][kt], b0, b1);
                MMAH(s[1][nt], qa[1][kt], b0, b1);
            }
        }
        __syncthreads();               // S3 (CTA): pbs visible; ks/rels free

        if (t + 1 < 8) issue_tiles(t + 1);
        cp_commit();

        // ---- bias gather + exp + partial sums ----
#pragma unroll
        for (int mi = 0; mi < 2; ++mi) {
            const int iA = rbase + mi * 16;
            const int iB = iA + 8;
#pragma unroll
            for (int nt = 0; nt < 4; ++nt) {
                const int jj = wn * 32 + nt * 8 + 2 * tig;
                const int oA0 = iA - jj + 63, oA1 = oA0 - 1;
                const int oB0 = iB - jj + 63, oB1 = oB0 - 1;
                const int pA0 = ((h ^ (oA0 >> 6)) << 6) | (oA0 & 63);
                const int pA1 = ((h ^ (oA1 >> 6)) << 6) | (oA1 & 63);
                const int pB0 = ((h ^ (oB0 >> 6)) << 6) | (oB0 & 63);
                const int pB1 = ((h ^ (oB1 >> 6)) << 6) | (oB1 & 63);
                float e0 = __expf((s[mi][nt][0] + pbs[iA * 132 + pA0]) * ATT_SCALE);
                float e1 = __expf((s[mi][nt][1] + pbs[iA * 132 + pA1]) * ATT_SCALE);
                float e2 = __expf((s[mi][nt][2] + pbs[iB * 132 + pB0]) * ATT_SCALE);
                float e3 = __expf((s[mi][nt][3] + pbs[iB * 132 + pB1]) * ATT_SCALE);
                s[mi][nt][0] = e0; s[mi][nt][1] = e1;
                s[mi][nt][2] = e2; s[mi][nt][3] = e3;
                lsum[mi][0] += e0 + e1;
                lsum[mi][1] += e2 + e3;
            }
        }
        bar_pair(pbar);                // S4 (pair)

        // ---- write P (fp16x2) into dead half (h^1): 32 words per row ----
        const int pc0 = (h ^ 1) * 64;
#pragma unroll
        for (int mi = 0; mi < 2; ++mi) {
            const int iA = rbase + mi * 16;
            const int iB = iA + 8;
#pragma unroll
            for (int nt = 0; nt < 4; ++nt) {
                const int widx = pc0 + wn * 16 + nt * 4 + tig;
                ps[iA * 132 + widx] = f2h2(s[mi][nt][0], s[mi][nt][1]);
                ps[iB * 132 + widx] = f2h2(s[mi][nt][2], s[mi][nt][3]);
            }
        }
        bar_pair(pbar);                // S5 (pair)

        // ---- O += P @ V  (V from transposed tile: rows d) ----
#pragma unroll
        for (int kt = 0; kt < 4; ++kt) {
            unsigned pa[2][4];
#pragma unroll
            for (int mi = 0; mi < 2; ++mi) {
                const int iA = rbase + mi * 16;
                const int iB = iA + 8;
                pa[mi][0] = ps[iA * 132 + pc0 + kt * 8 + tig    ];
                pa[mi][1] = ps[iB * 132 + pc0 + kt * 8 + tig    ];
                pa[mi][2] = ps[iA * 132 + pc0 + kt * 8 + tig + 4];
                pa[mi][3] = ps[iB * 132 + pc0 + kt * 8 + tig + 4];
            }
#pragma unroll
            for (int nt = 0; nt < 8; ++nt) {
                const int dr = nt * 8 + g;     // d row of vT tile
                const unsigned b0 = vs[dr * 36 + kt * 8 + tig    ];
                const unsigned b1 = vs[dr * 36 + kt * 8 + tig + 4];
                MMAH(o[0][nt], pa[0], b0, b1);
                MMAH(o[1][nt], pa[1], b0, b1);
            }
        }
    }

    // ---- epilogue: combine l, normalize, store g_ao fp16 ----
#pragma unroll
    for (int mi = 0; mi < 2; ++mi)
#pragma unroll
        for (int hf = 0; hf < 2; ++hf) {
            float v = lsum[mi][hf];
            v += __shfl_xor_sync(0xffffffffu, v, 1);
            v += __shfl_xor_sync(0xffffffffu, v, 2);
            lsum[mi][hf] = v;
        }

    __syncthreads();
    float* lsm = (float*)ks;
    if (tig == 0) {
#pragma unroll
        for (int mi = 0; mi < 2; ++mi) {
            lsm[(rbase + mi * 16    ) * 2 + wn] = lsum[mi][0];
            lsm[(rbase + mi * 16 + 8) * 2 + wn] = lsum[mi][1];
        }
    }
    __syncthreads();

    const int bb = bh >> 3, hh = bh & 7;
#pragma unroll
    for (int mi = 0; mi < 2; ++mi) {
        const int iA = rbase + mi * 16;
        const int iB = iA + 8;
        const float ilA = 1.f / (lsm[iA * 2] + lsm[iA * 2 + 1]);
        const float ilB = 1.f / (lsm[iB * 2] + lsm[iB * 2 + 1]);
        unsigned short* baseA = g_ao + ((size_t)bb * NSEQ + (i0 + iA)) * DMODEL + hh * DIMH;
        unsigned short* baseB = g_ao + ((size_t)bb * NSEQ + (i0 + iB)) * DMODEL + hh * DIMH;
#pragma unroll
        for (int nt = 0; nt < 8; ++nt) {
            const int c = nt * 8 + 2 * tig;
            *(unsigned*)&baseA[c] = f2h2(o[mi][nt][0] * ilA, o[mi][nt][1] * ilA);
            *(unsigned*)&baseB[c] = f2h2(o[mi][nt][2] * ilB, o[mi][nt][3] * ilB);
        }
    }
}

// ============================================================================
// launcher
// ============================================================================
extern "C" void kernel_launch(void* const* d_in, const int* in_sizes, int n_in,
                              void* d_out, int out_size)
{
    const float* x         = (const float*)d_in[0];  // [32,512,512]
    const float* W_qkv     = (const float*)d_in[1];  // [512,1536]
    const float* rel_table = (const float*)d_in[2];  // [1025,64]
    const float* W_out     = (const float*)d_in[3];  // [512,512]
    const float* b_out     = (const float*)d_in[4];  // [512]
    float* out = (float*)d_out;                      // [32,512,512]

    unsigned short *xh, *wqkvT, *woutT, *relh, *ao;
    cudaGetSymbolAddress((void**)&xh,    g_xh);
    cudaGetSymbolAddress((void**)&wqkvT, g_wqkvT);
    cudaGetSymbolAddress((void**)&woutT, g_woutT);
    cudaGetSymbolAddress((void**)&relh,  g_relh);
    cudaGetSymbolAddress((void**)&ao,    g_ao);

    // 0. pre-convert fp32 -> fp16 (weights transposed to [N][K])
    {
        int n4 = MROWS * DMODEL / 4;
        cvth_kernel<<<(n4 + 255) / 256, 256>>>((const float4*)x, (uint2*)xh, n4);
        n4 = 1025 * DIMH / 4;
        cvth_kernel<<<(n4 + 255) / 256, 256>>>((const float4*)rel_table, (uint2*)relh, n4);
        cvtTh_kernel<<<dim3(NQKV / 32, DMODEL / 32), dim3(32, 8)>>>(W_qkv, wqkvT, DMODEL, NQKV);
        cvtTh_kernel<<<dim3(DMODEL / 32, DMODEL / 32), dim3(32, 8)>>>(W_out, woutT, DMODEL, DMODEL);
    }

    // 1. QKV projection (fp16 mma, fused scatter; V transposed)
    cudaFuncSetAttribute(mm7_kernel<NQKV, 1>,
                         cudaFuncAttributeMaxDynamicSharedMemorySize, MM7_SMEM_BYTES);
    mm7_kernel<NQKV, 1><<<dim3(NQKV / 128, MROWS / 128), 128, MM7_SMEM_BYTES>>>(
        xh, wqkvT, nullptr, nullptr);

    // 2. fused fp16-mma attention (3 CTAs/SM)
    cudaFuncSetAttribute(attn7_kernel,
                         cudaFuncAttributeMaxDynamicSharedMemorySize, ATT7_SMEM_BYTES);
    attn7_kernel<<<dim3(BH, NSEQ / 64), 128, ATT7_SMEM_BYTES>>>();

    // 3. output projection (fp16 mma, fused bias)
    cudaFuncSetAttribute(mm7_kernel<DMODEL, 0>,
                         cudaFuncAttributeMaxDynamicSharedMemorySize, MM7_SMEM_BYTES);
    mm7_kernel<DMODEL, 0><<<dim3(DMODEL / 128, MROWS / 128), 128, MM7_SMEM_BYTES>>>(
        ao, woutT, b_out, out);
}

// round 15
// speedup vs baseline: 1.7328x; 1.0185x over previous
#include <cuda_runtime.h>
#include <cuda_fp16.h>

// Problem constants
#define HEADS   8
#define DIMH    64
#define NSEQ    512
#define BATCH   32
#define DMODEL  512
#define BH      (BATCH*HEADS)        // 256
#define NQKV    (3*HEADS*DIMH)       // 1536
#define MROWS   (BATCH*NSEQ)         // 16384
#define ATT_SCALE 0.125f             // 64^-0.5

// ---------------- scratch (device globals; no cudaMalloc allowed) -----------
// all fp16 bit patterns
__device__ __align__(16) unsigned short g_q    [BH*NSEQ*DIMH];
__device__ __align__(16) unsigned short g_k    [BH*NSEQ*DIMH];
__device__ __align__(16) unsigned short g_vT   [BH*DIMH*NSEQ];    // TRANSPOSED [bh][d][n]
__device__ __align__(16) unsigned short g_ao   [BATCH*NSEQ*DMODEL];
__device__ __align__(16) unsigned short g_xh   [MROWS*DMODEL];
__device__ __align__(16) unsigned short g_wqkvT[NQKV*DMODEL];     // [N][K]
__device__ __align__(16) unsigned short g_woutT[DMODEL*DMODEL];   // [N][K]
__device__ __align__(16) unsigned short g_relh [1025*DIMH];

// ---------------------------------------------------------------------------
// helpers
// ---------------------------------------------------------------------------
__device__ __forceinline__ unsigned f2h2(float lo, float hi) {
    unsigned r;
    asm("cvt.rn.f16x2.f32 %0, %1, %2;" : "=r"(r) : "f"(hi), "f"(lo));
    return r;
}
__device__ __forceinline__ unsigned short f2h(float x) {
    unsigned short r;
    asm("cvt.rn.f16.f32 %0, %1;" : "=h"(r) : "f"(x));
    return r;
}

// m16n8k16 fp16 mma, fp32 accumulate
__device__ __forceinline__ void mma_f16(float c[4], const unsigned a[4],
                                        unsigned b0, unsigned b1) {
    asm volatile(
        "mma.sync.aligned.m16n8k16.row.col.f32.f16.f16.f32 "
        "{%0,%1,%2,%3}, {%4,%5,%6,%7}, {%8,%9}, {%0,%1,%2,%3};\n"
        : "+f"(c[0]), "+f"(c[1]), "+f"(c[2]), "+f"(c[3])
        : "r"(a[0]), "r"(a[1]), "r"(a[2]), "r"(a[3]), "r"(b0), "r"(b1));
}
#define MMAH mma_f16

__device__ __forceinline__ void cp16(void* smem_dst, const void* gsrc) {
    unsigned s = (unsigned)__cvta_generic_to_shared(smem_dst);
    asm volatile("cp.async.cg.shared.global [%0], [%1], 16;\n" :: "r"(s), "l"(gsrc));
}
__device__ __forceinline__ void cp_commit() {
    asm volatile("cp.async.commit_group;\n");
}
template<int Nq>
__device__ __forceinline__ void cp_wait() {
    asm volatile("cp.async.wait_group %0;\n" :: "n"(Nq));
}
__device__ __forceinline__ void bar_pair(int id) {
    asm volatile("bar.sync %0, 64;" :: "r"(id) : "memory");
}

// ============================================================================
// cvt_all: single launch handling all fp32->fp16 conversions.
// Block ranges: [0,8192) x straight; [8192,8257) rel straight;
// [8257,9025) W_qkv transpose (C=1536); [9025,9281) W_out transpose (C=512).
// ============================================================================
#define CVT_XB   8192
#define CVT_RB   65
#define CVT_QB   768     // (1536/32) x (512/32)
#define CVT_OB   256     // (512/32) x (512/32)

__global__ void __launch_bounds__(256) cvt_all_kernel(
    const float* __restrict__ x, const float* __restrict__ rel,
    const float* __restrict__ Wq, const float* __restrict__ Wo)
{
    __shared__ float t[32][33];
    const int b   = blockIdx.x;
    const int tid = threadIdx.x;

    if (b < CVT_XB) {
        const int i = b * 256 + tid;            // exactly MROWS*DMODEL/4 float4s
        float4 v = ((const float4*)x)[i];
        ((uint2*)g_xh)[i] = make_uint2(f2h2(v.x, v.y), f2h2(v.z, v.w));
        return;
    }
    if (b < CVT_XB + CVT_RB) {
        const int i = (b - CVT_XB) * 256 + tid;
        if (i < 1025 * DIMH / 4) {
            float4 v = ((const float4*)rel)[i];
            ((uint2*)g_relh)[i] = make_uint2(f2h2(v.x, v.y), f2h2(v.z, v.w));
        }
        return;
    }
    // transpose branches: whole block takes same path; barrier is safe
    const float* src;
    unsigned short* dst;
    int R, C, bx, by;
    if (b < CVT_XB + CVT_RB + CVT_QB) {
        const int l = b - (CVT_XB + CVT_RB);
        src = Wq; dst = g_wqkvT; R = DMODEL; C = NQKV;
        bx = (l % 48) * 32; by = (l / 48) * 32;
    } else {
        const int l = b - (CVT_XB + CVT_RB + CVT_QB);
        src = Wo; dst = g_woutT; R = DMODEL; C = DMODEL;
        bx = (l % 16) * 32; by = (l / 16) * 32;
    }
    const int tx = tid & 31, ty = tid >> 5;     // (32, 8)
#pragma unroll
    for (int j = 0; j < 32; j += 8)
        t[ty + j][tx] = src[(size_t)(by + ty + j) * C + bx + tx];
    __syncthreads();
#pragma unroll
    for (int j = 0; j < 32; j += 8)
        dst[(size_t)(bx + ty + j) * R + by + tx] = f2h(t[tx][ty + j]);
}

// ============================================================================
// mm7: fp16 GEMM (unchanged from R14 — at mma.sync issue ceiling).
// ============================================================================
#define MM7_STAGE_W (2 * 128 * 20)
#define MM7_SMEM_BYTES (4 * MM7_STAGE_W * 4)

template<int N, int SCAT>   // SCAT: 0=bias epilogue, 1=qkv scatter
__global__ void __launch_bounds__(128, 2) mm7_kernel(
    const unsigned short* __restrict__ A, const unsigned short* __restrict__ Bt,
    const float* __restrict__ bias, float* __restrict__ Cout)
{
    constexpr int K = 512;
    constexpr int ITERS = 16;      // K / 32
    extern __shared__ unsigned sm[];

    const int tid  = threadIdx.x;
    const int w    = tid >> 5, lane = tid & 31;
    const int g    = lane >> 2, tig = lane & 3;
    const int wm   = w >> 1, wn = w & 1;
    const int bm   = blockIdx.y * 128;
    const int bn   = blockIdx.x * 128;

    auto issue = [&](int it) {
        const int s  = it & 3;
        const int k0 = it * 32;                 // halves
        unsigned* As = sm + s * MM7_STAGE_W;
        unsigned* Bs = As + 128 * 20;
#pragma unroll
        for (int j = 0; j < 4; ++j) {
            const int c  = tid + j * 128;       // 0..511
            const int r  = c >> 2;              // row 0..127
            const int ch = c & 3;               // 16B chunk in row
            cp16(&As[r * 20 + ch * 4], A  + (size_t)(bm + r) * K + k0 + ch * 8);
            cp16(&Bs[r * 20 + ch * 4], Bt + (size_t)(bn + r) * K + k0 + ch * 8);
        }
    };

    float acc[4][8][4];
#pragma unroll
    for (int mi = 0; mi < 4; ++mi)
#pragma unroll
        for (int ni = 0; ni < 8; ++ni)
#pragma unroll
            for (int e = 0; e < 4; ++e) acc[mi][ni][e] = 0.f;

    issue(0); cp_commit();
    issue(1); cp_commit();
    issue(2); cp_commit();

    for (int it = 0; it < ITERS; ++it) {
        const int cur = it & 3;
        cp_wait<2>();
        __syncthreads();

        if (it + 3 < ITERS) issue(it + 3);
        cp_commit();

        const unsigned* As = sm + cur * MM7_STAGE_W;
        const unsigned* Bs = As + 128 * 20;
#pragma unroll
        for (int kt = 0; kt < 2; ++kt) {
            unsigned af[4][4];
#pragma unroll
            for (int mi = 0; mi < 4; ++mi) {
                const int base = wm * 64 + mi * 16;
                af[mi][0] = As[(base + g    ) * 20 + kt * 8 + tig    ];
                af[mi][1] = As[(base + g + 8) * 20 + kt * 8 + tig    ];
                af[mi][2] = As[(base + g    ) * 20 + kt * 8 + tig + 4];
                af[mi][3] = As[(base + g + 8) * 20 + kt * 8 + tig + 4];
            }
#pragma unroll
            for (int ni = 0; ni < 8; ++ni) {
                const int nr = wn * 64 + ni * 8 + g;
                const unsigned b0 = Bs[nr * 20 + kt * 8 + tig    ];
                const unsigned b1 = Bs[nr * 20 + kt * 8 + tig + 4];
#pragma unroll
                for (int mi = 0; mi < 4; ++mi)
                    MMAH(acc[mi][ni], af[mi], b0, b1);
            }
        }
    }

    // ---- epilogue ----
    if (SCAT) {
        const int which = bn >> 9;
        if (which < 2) {
            unsigned short* dst = (which == 0) ? g_q : g_k;
#pragma unroll
            for (int mi = 0; mi < 4; ++mi) {
                const int r0  = bm + wm * 64 + mi * 16 + g;
                const int bb  = r0 >> 9;
                const int nn0 = r0 & 511;
#pragma unroll
                for (int ni = 0; ni < 8; ++ni) {
                    const int c  = bn + wn * 64 + ni * 8 + 2 * tig;
                    const int h  = (c & 511) >> 6;
                    const int dd = c & 63;
                    const size_t rowbase = (size_t)((bb << 3) + h) * NSEQ;
                    *(unsigned*)&dst[((rowbase + nn0    )) * DIMH + dd] =
                        f2h2(acc[mi][ni][0], acc[mi][ni][1]);
                    *(unsigned*)&dst[((rowbase + nn0 + 8)) * DIMH + dd] =
                        f2h2(acc[mi][ni][2], acc[mi][ni][3]);
                }
            }
        } else {
            // V: transpose through smem, then coalesced writes to g_vT [bh][d][n]
            __syncthreads();
            unsigned short* tsm = (unsigned short*)sm;   // 128 x 136 halves
#pragma unroll
            for (int mi = 0; mi < 4; ++mi) {
                const int lr = wm * 64 + mi * 16 + g;
#pragma unroll
                for (int ni = 0; ni < 8; ++ni) {
                    const int lc = wn * 64 + ni * 8 + 2 * tig;
                    tsm[(lc    ) * 136 + lr    ] = f2h(acc[mi][ni][0]);
                    tsm[(lc + 1) * 136 + lr    ] = f2h(acc[mi][ni][1]);
                    tsm[(lc    ) * 136 + lr + 8] = f2h(acc[mi][ni][2]);
                    tsm[(lc + 1) * 136 + lr + 8] = f2h(acc[mi][ni][3]);
                }
            }
            __syncthreads();
            const int lc  = tid;                 // transposed row 0..127
            const int c   = bn + lc;
            const int h   = (c & 511) >> 6;
            const int dd  = c & 63;
            const int bb  = bm >> 9;
            const int nnb = bm & 511;
            unsigned short* dstp =
                g_vT + ((size_t)((bb << 3) + h) * DIMH + dd) * NSEQ + nnb;
#pragma unroll
            for (int u = 0; u < 16; ++u)
                *(uint4*)(dstp + u * 8) = *(const uint4*)(tsm + lc * 136 + u * 8);
        }
    } else {
#pragma unroll
        for (int mi = 0; mi < 4; ++mi) {
            const int r = bm + wm * 64 + mi * 16 + g;
#pragma unroll
            for (int ni = 0; ni < 8; ++ni) {
                const int c = bn + wn * 64 + ni * 8 + 2 * tig;
                const float2 bv = *(const float2*)&bias[c];
                *(float2*)&Cout[(size_t)r * N + c] =
                    make_float2(acc[mi][ni][0] + bv.x, acc[mi][ni][1] + bv.y);
                *(float2*)&Cout[(size_t)(r + 8) * N + c] =
                    make_float2(acc[mi][ni][2] + bv.x, acc[mi][ni][3] + bv.y);
            }
        }
    }
}

// ============================================================================
// attn8: R14's attn7 (3 CTAs/SM) + early V issue: V(t+1) issued right after
// S2 (vs[h^1] provably free: PV(t-1) completed before S2), so the V load
// shadows PB+QK as well. K/rel still issued after S3.
// ============================================================================
#define ATT8_SMEM_WORDS (2304 + 2304 + 4608 + 8448)
#define ATT8_SMEM_BYTES (ATT8_SMEM_WORDS * 4)

__global__ void __launch_bounds__(128, 3) attn8_kernel()
{
    extern __shared__ unsigned smu[];
    unsigned* rels  = smu;                    // 64 x 36 (Q staging alias)
    unsigned* ks    = smu + 2304;             // 64 x 36 (l-exchange alias)
    unsigned* vsbuf = smu + 4608;             // 2 x 64 x 36
    float*    pbs   = (float*)(smu + 9216);   // 64 x 132
    unsigned* ps    = (unsigned*)pbs;

    const int tid  = threadIdx.x;
    const int w    = tid >> 5;
    const int lane = tid & 31;
    const int g    = lane >> 2;
    const int tig  = lane & 3;
    const int wm   = w >> 1, wn = w & 1;

    const int bh = blockIdx.x;
    const int qb = blockIdx.y;
    const int i0 = qb * 64;
    const int rbase = wm * 32 + g;
    const int pbar  = wm + 1;

    const unsigned short* qg = g_q  + ((size_t)bh * NSEQ + i0) * DIMH;
    const unsigned short* kg = g_k  + (size_t)bh * NSEQ * DIMH;
    const unsigned short* vg = g_vT + (size_t)bh * DIMH * NSEQ;
    const unsigned short* rg = g_relh;

    auto copy_tile = [&](unsigned* dst, const unsigned short* src, int srcstride) {
#pragma unroll
        for (int k = 0; k < 4; ++k) {
            const int c  = tid + k * 128;      // chunk 0..511
            const int r  = c >> 3;             // row 0..63
            const int ch = c & 7;              // 16B chunk (8 halves)
            cp16(&dst[r * 36 + ch * 4], src + (size_t)r * srcstride + ch * 8);
        }
    };

    auto issue_kr = [&](int t) {               // K + rel only
        const int j0 = t * 64;
        copy_tile(ks, kg + (size_t)j0 * DIMH, 64);
        copy_tile(rels, rg + (size_t)(i0 + 449 - j0) * DIMH, 64);
    };
    auto issue_v = [&](int t) {
        copy_tile(vsbuf + (t & 1) * 2304, vg + t * 64, NSEQ);
    };

    // ---- stage Q ----
    copy_tile(rels, qg, 64);
    cp_commit();
    cp_wait<0>();
    __syncthreads();

    // ---- Q A-fragments (4 k16 chunks) ----
    unsigned qa[2][4][4];
#pragma unroll
    for (int mi = 0; mi < 2; ++mi) {
        const int r0 = rbase + mi * 16;
#pragma unroll
        for (int kt = 0; kt < 4; ++kt) {
            qa[mi][kt][0] = rels[ r0      * 36 + kt * 8 + tig    ];
            qa[mi][kt][1] = rels[(r0 + 8) * 36 + kt * 8 + tig    ];
            qa[mi][kt][2] = rels[ r0      * 36 + kt * 8 + tig + 4];
            qa[mi][kt][3] = rels[(r0 + 8) * 36 + kt * 8 + tig + 4];
        }
    }
    __syncthreads();   // rels free

    // ---- prologue: rel chunk(-1) -> pbs half 1 ----
    {
        copy_tile(rels, rg + (size_t)(i0 + 513) * DIMH, 64);
        cp_commit();
        cp_wait<0>();
        __syncthreads();
#pragma unroll
        for (int nt = 0; nt < 4; ++nt) {
            float a0[4] = {0.f,0.f,0.f,0.f}, a1[4] = {0.f,0.f,0.f,0.f};
            const int dr = wn * 32 + nt * 8 + g;
#pragma unroll
            for (int kt = 0; kt < 4; ++kt) {
                const unsigned b0 = rels[dr * 36 + kt * 8 + tig    ];
                const unsigned b1 = rels[dr * 36 + kt * 8 + tig + 4];
                MMAH(a0, qa[0][kt], b0, b1);
                MMAH(a1, qa[1][kt], b0, b1);
            }
            const int col = 64 + wn * 32 + nt * 8 + 2 * tig;
            *(float2*)&pbs[(rbase     ) * 132 + col] = make_float2(a0[0], a0[1]);
            *(float2*)&pbs[(rbase +  8) * 132 + col] = make_float2(a0[2], a0[3]);
            *(float2*)&pbs[(rbase + 16) * 132 + col] = make_float2(a1[0], a1[1]);
            *(float2*)&pbs[(rbase + 24) * 132 + col] = make_float2(a1[2], a1[3]);
        }
    }
    __syncthreads();

    issue_kr(0);
    issue_v(0);
    cp_commit();

    float lsum[2][2] = {{0.f, 0.f}, {0.f, 0.f}};
    float o[2][8][4];
#pragma unroll
    for (int mi = 0; mi < 2; ++mi)
#pragma unroll
        for (int nt = 0; nt < 8; ++nt)
#pragma unroll
            for (int e = 0; e < 4; ++e) o[mi][nt][e] = 0.f;

    for (int t = 0; t < 8; ++t) {
        const int h = t & 1;
        const unsigned* vs = vsbuf + h * 2304;

        cp_wait<0>();
        __syncthreads();               // S2: tiles t ready; all past PV(t-1)

        // ---- early V(t+1): vs[h^1] free (PV(t-1) done at S2) ----
        if (t + 1 < 8) { issue_v(t + 1); cp_commit(); }

        // ---- PB new chunk -> pbs half h ----
#pragma unroll
        for (int nt = 0; nt < 4; ++nt) {
            float a0[4] = {0.f,0.f,0.f,0.f}, a1[4] = {0.f,0.f,0.f,0.f};
            const int dr = wn * 32 + nt * 8 + g;
#pragma unroll
            for (int kt = 0; kt < 4; ++kt) {
                const unsigned b0 = rels[dr * 36 + kt * 8 + tig    ];
                const unsigned b1 = rels[dr * 36 + kt * 8 + tig + 4];
                MMAH(a0, qa[0][kt], b0, b1);
                MMAH(a1, qa[1][kt], b0, b1);
            }
            const int col = h * 64 + wn * 32 + nt * 8 + 2 * tig;
            *(float2*)&pbs[(rbase     ) * 132 + col] = make_float2(a0[0], a0[1]);
            *(float2*)&pbs[(rbase +  8) * 132 + col] = make_float2(a0[2], a0[3]);
            *(float2*)&pbs[(rbase + 16) * 132 + col] = make_float2(a1[0], a1[1]);
            *(float2*)&pbs[(rbase + 24) * 132 + col] = make_float2(a1[2], a1[3]);
        }

        // ---- QK ----
        float s[2][4][4];
#pragma unroll
        for (int nt = 0; nt < 4; ++nt) {
            const int jr = wn * 32 + nt * 8 + g;
#pragma unroll
            for (int mi = 0; mi < 2; ++mi)
                s[mi][nt][0] = s[mi][nt][1] = s[mi][nt][2] = s[mi][nt][3] = 0.f;
#pragma unroll
            for (int kt = 0; kt < 4; ++kt) {
                const unsigned b0 = ks[jr * 36 + kt * 8 + tig    ];
                const unsigned b1 = ks[jr * 36 + kt * 8 + tig + 4];
                MMAH(s[0][nt], qa[0][kt], b0, b1);
                MMAH(s[1][nt], qa[1][kt], b0, b1);
            }
        }
        __syncthreads();               // S3 (CTA): pbs visible; ks/rels free

        if (t + 1 < 8) issue_kr(t + 1);
        cp_commit();

        // ---- bias gather + exp + partial sums ----
#pragma unroll
        for (int mi = 0; mi < 2; ++mi) {
            const int iA = rbase + mi * 16;
            const int iB = iA + 8;
#pragma unroll
            for (int nt = 0; nt < 4; ++nt) {
                const int jj = wn * 32 + nt * 8 + 2 * tig;
                const int oA0 = iA - jj + 63, oA1 = oA0 - 1;
                const int oB0 = iB - jj + 63, oB1 = oB0 - 1;
                const int pA0 = ((h ^ (oA0 >> 6)) << 6) | (oA0 & 63);
                const int pA1 = ((h ^ (oA1 >> 6)) << 6) | (oA1 & 63);
                const int pB0 = ((h ^ (oB0 >> 6)) << 6) | (oB0 & 63);
                const int pB1 = ((h ^ (oB1 >> 6)) << 6) | (oB1 & 63);
                float e0 = __expf((s[mi][nt][0] + pbs[iA * 132 + pA0]) * ATT_SCALE);
                float e1 = __expf((s[mi][nt][1] + pbs[iA * 132 + pA1]) * ATT_SCALE);
                float e2 = __expf((s[mi][nt][2] + pbs[iB * 132 + pB0]) * ATT_SCALE);
                float e3 = __expf((s[mi][nt][3] + pbs[iB * 132 + pB1]) * ATT_SCALE);
                s[mi][nt][0] = e0; s[mi][nt][1] = e1;
                s[mi][nt][2] = e2; s[mi][nt][3] = e3;
                lsum[mi][0] += e0 + e1;
                lsum[mi][1] += e2 + e3;
            }
        }
        bar_pair(pbar);                // S4 (pair)

        // ---- write P (fp16x2) into dead half (h^1) ----
        const int pc0 = (h ^ 1) * 64;
#pragma unroll
        for (int mi = 0; mi < 2; ++mi) {
            const int iA = rbase + mi * 16;
            const int iB = iA + 8;
#pragma unroll
            for (int nt = 0; nt < 4; ++nt) {
                const int widx = pc0 + wn * 16 + nt * 4 + tig;
                ps[iA * 132 + widx] = f2h2(s[mi][nt][0], s[mi][nt][1]);
                ps[iB * 132 + widx] = f2h2(s[mi][nt][2], s[mi][nt][3]);
            }
        }
        bar_pair(pbar);                // S5 (pair)

        // ---- O += P @ V ----
#pragma unroll
        for (int kt = 0; kt < 4; ++kt) {
            unsigned pa[2][4];
#pragma unroll
            for (int mi = 0; mi < 2; ++mi) {
                const int iA = rbase + mi * 16;
                const int iB = iA + 8;
                pa[mi][0] = ps[iA * 132 + pc0 + kt * 8 + tig    ];
                pa[mi][1] = ps[iB * 132 + pc0 + kt * 8 + tig    ];
                pa[mi][2] = ps[iA * 132 + pc0 + kt * 8 + tig + 4];
                pa[mi][3] = ps[iB * 132 + pc0 + kt * 8 + tig + 4];
            }
#pragma unroll
            for (int nt = 0; nt < 8; ++nt) {
                const int dr = nt * 8 + g;     // d row of vT tile
                const unsigned b0 = vs[dr * 36 + kt * 8 + tig    ];
                const unsigned b1 = vs[dr * 36 + kt * 8 + tig + 4];
                MMAH(o[0][nt], pa[0], b0, b1);
                MMAH(o[1][nt], pa[1], b0, b1);
            }
        }
    }

    // ---- epilogue: combine l, normalize, store g_ao fp16 ----
#pragma unroll
    for (int mi = 0; mi < 2; ++mi)
#pragma unroll
        for (int hf = 0; hf < 2; ++hf) {
            float v = lsum[mi][hf];
            v += __shfl_xor_sync(0xffffffffu, v, 1);
            v += __shfl_xor_sync(0xffffffffu, v, 2);
            lsum[mi][hf] = v;
        }

    __syncthreads();
    float* lsm = (float*)ks;
    if (tig == 0) {
#pragma unroll
        for (int mi = 0; mi < 2; ++mi) {
            lsm[(rbase + mi * 16    ) * 2 + wn] = lsum[mi][0];
            lsm[(rbase + mi * 16 + 8) * 2 + wn] = lsum[mi][1];
        }
    }
    __syncthreads();

    const int bb = bh >> 3, hh = bh & 7;
#pragma unroll
    for (int mi = 0; mi < 2; ++mi) {
        const int iA = rbase + mi * 16;
        const int iB = iA + 8;
        const float ilA = 1.f / (lsm[iA * 2] + lsm[iA * 2 + 1]);
        const float ilB = 1.f / (lsm[iB * 2] + lsm[iB * 2 + 1]);
        unsigned short* baseA = g_ao + ((size_t)bb * NSEQ + (i0 + iA)) * DMODEL + hh * DIMH;
        unsigned short* baseB = g_ao + ((size_t)bb * NSEQ + (i0 + iB)) * DMODEL + hh * DIMH;
#pragma unroll
        for (int nt = 0; nt < 8; ++nt) {
            const int c = nt * 8 + 2 * tig;
            *(unsigned*)&baseA[c] = f2h2(o[mi][nt][0] * ilA, o[mi][nt][1] * ilA);
            *(unsigned*)&baseB[c] = f2h2(o[mi][nt][2] * ilB, o[mi][nt][3] * ilB);
        }
    }
}

// ============================================================================
// launcher
// ============================================================================
extern "C" void kernel_launch(void* const* d_in, const int* in_sizes, int n_in,
                              void* d_out, int out_size)
{
    const float* x         = (const float*)d_in[0];  // [32,512,512]
    const float* W_qkv     = (const float*)d_in[1];  // [512,1536]
    const float* rel_table = (const float*)d_in[2];  // [1025,64]
    const float* W_out     = (const float*)d_in[3];  // [512,512]
    const float* b_out     = (const float*)d_in[4];  // [512]
    float* out = (float*)d_out;                      // [32,512,512]

    unsigned short *xh, *wqkvT, *woutT, *ao;
    cudaGetSymbolAddress((void**)&xh,    g_xh);
    cudaGetSymbolAddress((void**)&wqkvT, g_wqkvT);
    cudaGetSymbolAddress((void**)&woutT, g_woutT);
    cudaGetSymbolAddress((void**)&ao,    g_ao);

    // 0. single-launch pre-convert (x, rel straight; weights transposed)
    cvt_all_kernel<<<CVT_XB + CVT_RB + CVT_QB + CVT_OB, 256>>>(
        x, rel_table, W_qkv, W_out);

    // 1. QKV projection (fp16 mma, fused scatter; V transposed)
    cudaFuncSetAttribute(mm7_kernel<NQKV, 1>,
                         cudaFuncAttributeMaxDynamicSharedMemorySize, MM7_SMEM_BYTES);
    mm7_kernel<NQKV, 1><<<dim3(NQKV / 128, MROWS / 128), 128, MM7_SMEM_BYTES>>>(
        xh, wqkvT, nullptr, nullptr);

    // 2. fused fp16-mma attention (3 CTAs/SM, early-V pipeline)
    cudaFuncSetAttribute(attn8_kernel,
                         cudaFuncAttributeMaxDynamicSharedMemorySize, ATT8_SMEM_BYTES);
    attn8_kernel<<<dim3(BH, NSEQ / 64), 128, ATT8_SMEM_BYTES>>>();

    // 3. output projection (fp16 mma, fused bias)
    cudaFuncSetAttribute(mm7_kernel<DMODEL, 0>,
                         cudaFuncAttributeMaxDynamicSharedMemorySize, MM7_SMEM_BYTES);
    mm7_kernel<DMODEL, 0><<<dim3(DMODEL / 128, MROWS / 128), 128, MM7_SMEM_BYTES>>>(
        ao, woutT, b_out, out);
}